// round 6
// baseline (speedup 1.0000x reference)
#include <cuda_runtime.h>
#include <math.h>
#include <stdint.h>

// Problem constants
#define Nn   32
#define Cc   64
#define Tt   64
#define Vv   204
#define Hh   3
#define QKd  16
#define Pp   13056
#define OQKV 96
#define HC   192

// ---------------- scratch (padded where edge chunks over-read) ----------------
__device__ float d_h   [(size_t)Nn * Cc * Pp + 64];   // gcn conv out; later z
__device__ float d_g   [(size_t)Nn * Cc * Pp + 64];
__device__ float d_qk  [(size_t)Nn * OQKV * Pp + 64];
__device__ float d_wpe [(size_t)OQKV * Pp];
__device__ float d_att [(size_t)Nn * Hh * Tt * Tt];
__device__ float d_attp[(size_t)4 * Nn * Hh * Tt * Tt];
__device__ float d_G2  [(size_t)Nn * HC * Pp + 64];
__device__ float d_wt  [4096 + 6144 + 4096 + 12288];  // tf32: gcn | qkv | ff | w2
__device__ float d_A2  [224 * 208];                   // tf32 zero-padded adjacency [u(224)][v(208)]

#define WT_GCN 0
#define WT_QKV 4096
#define WT_FF  10240
#define WT_W2  14336

enum { MODE_BIAS = 0, MODE_ADD2D = 1, MODE_BN_RES_LEAKY = 2, MODE_NONE = 3 };

// ---------------- helpers ----------------
__device__ __forceinline__ unsigned cvt_tf32(float f) {
    unsigned u;
    asm("cvt.rna.tf32.f32 %0, %1;" : "=r"(u) : "f"(f));
    return u;
}
__device__ __forceinline__ float rna_f(float f) { return __uint_as_float(cvt_tf32(f)); }

__device__ __forceinline__ void mma8(float* d, const unsigned* a, const unsigned* b) {
    asm volatile(
        "mma.sync.aligned.m16n8k8.row.col.f32.tf32.tf32.f32 "
        "{%0,%1,%2,%3},{%4,%5,%6,%7},{%8,%9},{%0,%1,%2,%3};"
        : "+f"(d[0]), "+f"(d[1]), "+f"(d[2]), "+f"(d[3])
        : "r"(a[0]), "r"(a[1]), "r"(a[2]), "r"(a[3]), "r"(b[0]), "r"(b[1]));
}

__device__ __forceinline__ uint32_t smem_u32(const void* p) {
    return (uint32_t)__cvta_generic_to_shared(p);
}
__device__ __forceinline__ void cpa16(uint32_t dst, const void* src) {
    asm volatile("cp.async.cg.shared.global [%0],[%1],16;" :: "r"(dst), "l"(src));
}
__device__ __forceinline__ void cpa16z(uint32_t dst, const void* src, int sz) {
    asm volatile("cp.async.cg.shared.global [%0],[%1],16,%2;" :: "r"(dst), "l"(src), "r"(sz));
}
#define CP_COMMIT() asm volatile("cp.async.commit_group;")
#define CP_WAIT2()  asm volatile("cp.async.wait_group 2;")

// ============================================================================
// prep: tf32-convert all small operands once per call
// ============================================================================
__global__ void prep_kernel(const float* __restrict__ gcn_w, const float* __restrict__ qkv_w,
                            const float* __restrict__ ff_w, const float* __restrict__ on_w,
                            const float* __restrict__ A,
                            float* __restrict__ wt, float* __restrict__ A2)
{
    int i = blockIdx.x * 256 + threadIdx.x;
    if (i < 4096) { wt[WT_GCN + i] = rna_f(gcn_w[i]); return; }
    i -= 4096;
    if (i < 6144) { wt[WT_QKV + i] = rna_f(qkv_w[i]); return; }
    i -= 6144;
    if (i < 4096) { wt[WT_FF + i] = rna_f(ff_w[i]); return; }
    i -= 4096;
    if (i < 12288) {
        int o = i >> 6, cc = i & 63;
        int s = o >> 6, c = o & 63;
        wt[WT_W2 + i] = rna_f(on_w[(size_t)c * HC + s * 64 + cc]);
        return;
    }
    i -= 12288;
    if (i < 224 * 208) {
        int u = i / 208, v = i % 208;
        A2[i] = (u < 204 && v < 204) ? rna_f(A[(size_t)u * 204 + v]) : 0.f;
    }
}

// ============================================================================
// conv_mma: out[n,o,p] = sum_c W[o,c]*in[n,c,p]
// 512 threads, 16 warps = 4(M)x4(N). CTA tile M=64, N=256, k-chunk 16, 4-stage.
// Warp tile m16 x n64 -> acc 32 regs.
// ============================================================================
#define CV_ASZ (64 * 20)
#define CV_BSZ (16 * 264)
#define CV_SMEM (4 * (CV_ASZ + CV_BSZ) * 4)

template <int MODE, int ROUND>
__global__ __launch_bounds__(512, 2)
void conv_mma(const float* __restrict__ in, const float* __restrict__ Wt,
              const float* __restrict__ bias, const float* __restrict__ add2d,
              const float* __restrict__ res,
              const float* __restrict__ bng, const float* __restrict__ bnb,
              const float* __restrict__ bnm, const float* __restrict__ bnv,
              float* __restrict__ out, int Kc, int Oc)
{
    extern __shared__ float sm[];
    float* As = sm;                 // 4 stages [64][20]
    float* Bs = sm + 4 * CV_ASZ;    // 4 stages [16][264]

    const int n  = blockIdx.z;
    const int pt = blockIdx.x * 256;
    const int ot = blockIdx.y * 64;
    const int tid = threadIdx.x, lane = tid & 31, warp = tid >> 5;
    const int wm = warp & 3, wn = warp >> 2;
    const int m0 = wm * 16, n0 = wn * 64;
    const int lr = lane >> 2, kc = lane & 3;

    const float* inN = in + (size_t)n * Kc * Pp + pt;
    const int NCH = Kc >> 4;

    float acc[8][4];
    #pragma unroll
    for (int j = 0; j < 8; j++)
        #pragma unroll
        for (int q = 0; q < 4; q++) acc[j][q] = 0.f;

    auto prefetch = [&](int c, int stage) {
        float* BsS = Bs + stage * CV_BSZ;
        const float* bsrc = inN + (size_t)(c * 16) * Pp;
        #pragma unroll
        for (int i = 0; i < 2; i++) {
            int e = tid + 512 * i;
            int k = e >> 6, grp = e & 63;
            cpa16(smem_u32(&BsS[k * 264 + grp * 4]), bsrc + (size_t)k * Pp + grp * 4);
        }
        if (tid < 256) {
            float* AsS = As + stage * CV_ASZ;
            int arow = tid >> 2, agrp = tid & 3;
            int o = ot + arow;
            int ok = (o < Oc);
            cpa16z(smem_u32(&AsS[arow * 20 + agrp * 4]),
                   ok ? (Wt + (size_t)o * Kc + c * 16 + agrp * 4) : Wt, ok ? 16 : 0);
        }
    };

    prefetch(0, 0); CP_COMMIT();
    if (NCH > 1) prefetch(1, 1);
    CP_COMMIT();

    for (int c = 0; c < NCH; c++) {
        if (c + 2 < NCH) prefetch(c + 2, (c + 2) & 3);
        CP_COMMIT();
        CP_WAIT2();
        __syncthreads();

        const float* AsS = As + (c & 3) * CV_ASZ;
        const float* BsS = Bs + (c & 3) * CV_BSZ;
        #pragma unroll
        for (int g = 0; g < 2; g++) {
            unsigned a[4];
            a[0] = __float_as_uint(AsS[(m0 + lr    ) * 20 + g * 8 + kc    ]);
            a[1] = __float_as_uint(AsS[(m0 + lr + 8) * 20 + g * 8 + kc    ]);
            a[2] = __float_as_uint(AsS[(m0 + lr    ) * 20 + g * 8 + kc + 4]);
            a[3] = __float_as_uint(AsS[(m0 + lr + 8) * 20 + g * 8 + kc + 4]);
            #pragma unroll
            for (int j = 0; j < 8; j++) {
                unsigned b[2];
                b[0] = __float_as_uint(BsS[(g * 8 + kc    ) * 264 + n0 + 8 * j + lr]);
                b[1] = __float_as_uint(BsS[(g * 8 + kc + 4) * 264 + n0 + 8 * j + lr]);
                mma8(acc[j], a, b);
            }
        }
    }

    #pragma unroll
    for (int half = 0; half < 2; half++) {
        int o = ot + m0 + lr + half * 8;
        if (o >= Oc) continue;
        size_t obase = ((size_t)n * Oc + o) * Pp;
        if (MODE == MODE_NONE) {
            #pragma unroll
            for (int j = 0; j < 8; j++) {
                int p = pt + n0 + 8 * j + 2 * kc;
                float va = acc[j][half * 2], vb = acc[j][half * 2 + 1];
                if (ROUND) { va = rna_f(va); vb = rna_f(vb); }
                *(float2*)(out + obase + p) = make_float2(va, vb);
            }
        } else if (MODE == MODE_BIAS) {
            float b = bias[o];
            #pragma unroll
            for (int j = 0; j < 8; j++) {
                int p = pt + n0 + 8 * j + 2 * kc;
                float va = acc[j][half * 2] + b, vb = acc[j][half * 2 + 1] + b;
                if (ROUND) { va = rna_f(va); vb = rna_f(vb); }
                *(float2*)(out + obase + p) = make_float2(va, vb);
            }
        } else if (MODE == MODE_ADD2D) {
            size_t abase = (size_t)o * Pp;
            #pragma unroll
            for (int j = 0; j < 8; j++) {
                int p = pt + n0 + 8 * j + 2 * kc;
                float2 av = *(const float2*)(add2d + abase + p);
                float va = acc[j][half * 2] + av.x, vb = acc[j][half * 2 + 1] + av.y;
                if (ROUND) { va = rna_f(va); vb = rna_f(vb); }
                *(float2*)(out + obase + p) = make_float2(va, vb);
            }
        } else { // MODE_BN_RES_LEAKY
            float s  = bng[o] * rsqrtf(bnv[o] + 1e-5f);
            float sh = bnb[o] - bnm[o] * s + bias[o] * s;
            #pragma unroll
            for (int j = 0; j < 8; j++) {
                int p = pt + n0 + 8 * j + 2 * kc;
                float2 rv = *(const float2*)(res + obase + p);
                float va = acc[j][half * 2]     * s + sh + rv.x;
                float vb = acc[j][half * 2 + 1] * s + sh + rv.y;
                va = (va > 0.f) ? va : 0.1f * va;
                vb = (vb > 0.f) ? vb : 0.1f * vb;
                if (ROUND) { va = rna_f(va); vb = rna_f(vb); }
                *(float2*)(out + obase + p) = make_float2(va, vb);
            }
        }
    }
}

// ============================================================================
// adj_mma: g[r,u] = relu(bn_c(sum_v h[r,v]*A2[u,v]) + x[r,u])
// 512 threads, 16 warps = 4(M)x4(N). M=64(r), N=224(u pad), K=208 (13 chunks).
// Warp tile m16 x n56 -> acc 28 regs.
// ============================================================================
#define AD_ASZ (64 * 20)
#define AD_BSZ (224 * 20)
#define AD_SMEM (4 * (AD_ASZ + AD_BSZ) * 4)

__global__ __launch_bounds__(512, 2)
void adj_mma(const float* __restrict__ h, const float* __restrict__ A2,
             const float* __restrict__ x,
             const float* __restrict__ bng, const float* __restrict__ bnb,
             const float* __restrict__ bnm, const float* __restrict__ bnv,
             float* __restrict__ out)
{
    extern __shared__ float sm[];
    float* As = sm;                 // 4 stages [64][20]   (h rows)
    float* Bs = sm + 4 * AD_ASZ;    // 4 stages [224][20]  (A2 rows)

    const int rt = blockIdx.x * 64;
    const int tid = threadIdx.x, lane = tid & 31, warp = tid >> 5;
    const int wm = warp & 3, wn = warp >> 2;
    const int m0 = wm * 16, n0 = wn * 56;
    const int lr = lane >> 2, kc = lane & 3;

    const int ch  = (rt >> 6) & 63;
    const float s  = bng[ch] * rsqrtf(bnv[ch] + 1e-5f);
    const float sh = bnb[ch] - bnm[ch] * s;

    float acc[7][4];
    #pragma unroll
    for (int j = 0; j < 7; j++)
        #pragma unroll
        for (int q = 0; q < 4; q++) acc[j][q] = 0.f;

    const int NCH = 13;

    auto prefetch = [&](int c, int stage) {
        float* BsS = Bs + stage * AD_BSZ;
        #pragma unroll
        for (int i = 0; i < 2; i++) {
            int e = tid + 512 * i;
            if (e < 896) {
                int u = e >> 2, grp = e & 3;
                cpa16(smem_u32(&BsS[u * 20 + grp * 4]), A2 + (size_t)u * 208 + c * 16 + grp * 4);
            }
        }
        if (tid < 256) {
            float* AsS = As + stage * AD_ASZ;
            int arow = tid >> 2, agrp = tid & 3;
            cpa16(smem_u32(&AsS[arow * 20 + agrp * 4]),
                  h + (size_t)(rt + arow) * 204 + c * 16 + agrp * 4);  // edge over-read x A2-zero-cols
        }
    };

    prefetch(0, 0); CP_COMMIT();
    prefetch(1, 1); CP_COMMIT();

    for (int c = 0; c < NCH; c++) {
        if (c + 2 < NCH) prefetch(c + 2, (c + 2) & 3);
        CP_COMMIT();
        CP_WAIT2();
        __syncthreads();

        const float* AsS = As + (c & 3) * AD_ASZ;
        const float* BsS = Bs + (c & 3) * AD_BSZ;
        #pragma unroll
        for (int g = 0; g < 2; g++) {
            unsigned a[4];
            a[0] = __float_as_uint(AsS[(m0 + lr    ) * 20 + g * 8 + kc    ]);
            a[1] = __float_as_uint(AsS[(m0 + lr + 8) * 20 + g * 8 + kc    ]);
            a[2] = __float_as_uint(AsS[(m0 + lr    ) * 20 + g * 8 + kc + 4]);
            a[3] = __float_as_uint(AsS[(m0 + lr + 8) * 20 + g * 8 + kc + 4]);
            #pragma unroll
            for (int j = 0; j < 7; j++) {
                unsigned b[2];
                b[0] = __float_as_uint(BsS[(n0 + 8 * j + lr) * 20 + g * 8 + kc    ]);
                b[1] = __float_as_uint(BsS[(n0 + 8 * j + lr) * 20 + g * 8 + kc + 4]);
                mma8(acc[j], a, b);
            }
        }
    }

    #pragma unroll
    for (int half = 0; half < 2; half++) {
        int r = rt + m0 + lr + half * 8;
        size_t rbase = (size_t)r * 204;
        #pragma unroll
        for (int j = 0; j < 7; j++) {
            int u = n0 + 8 * j + 2 * kc;
            if (u < 204) {
                float2 xv = *(const float2*)(x + rbase + u);
                float va = acc[j][half * 2]     * s + sh + xv.x;
                float vb = acc[j][half * 2 + 1] * s + sh + xv.y;
                *(float2*)(out + rbase + u) =
                    make_float2(rna_f(fmaxf(va, 0.f)), rna_f(fmaxf(vb, 0.f)));
            }
        }
    }
}

// ============================================================================
// attn_mma: part[z,n,h,t,q] = sum_{c in 4-chunk z, v} q[c,t,v]*k[c,q,v] (tf32)
// 256 threads (unchanged structure), 4 CTAs/SM target.
// ============================================================================
#define AT_QSZ (64 * 20)
#define AT_SMEM (4 * 2 * AT_QSZ * 4)

__global__ __launch_bounds__(256, 4)
void attn_mma(const float* __restrict__ qk, float* __restrict__ part)
{
    extern __shared__ float sm[];
    float* Qs = sm;
    float* Ks = sm + 4 * AT_QSZ;

    const int hh = blockIdx.x, n = blockIdx.y, z = blockIdx.z;
    const int cc0 = z * 4;
    const int tid = threadIdx.x, lane = tid & 31, warp = tid >> 5;
    const int wm = warp & 3, wn = warp >> 2;
    const int m0 = wm * 16, nb0 = wn * 32;
    const int lr = lane >> 2, kc = lane & 3;

    const float* qbase = qk + ((size_t)n * OQKV + hh * QKd) * Pp;
    const float* kbase = qk + ((size_t)n * OQKV + Hh * QKd + hh * QKd) * Pp;

    const int arow = tid >> 2, agrp = tid & 3;
    const int NCH = 52;

    float acc[4][4];
    #pragma unroll
    for (int j = 0; j < 4; j++)
        #pragma unroll
        for (int q = 0; q < 4; q++) acc[j][q] = 0.f;

    auto prefetch = [&](int c, int stage) {
        int ci = cc0 + (c / 13);
        int vb = (c % 13) * 16;
        int v = vb + agrp * 4;
        int ok = (v < 204);
        const float* qs = qbase + (size_t)ci * Pp + (size_t)arow * 204 + v;
        const float* ks = kbase + (size_t)ci * Pp + (size_t)arow * 204 + v;
        cpa16z(smem_u32(&Qs[stage * AT_QSZ + arow * 20 + agrp * 4]), ok ? qs : qk, ok ? 16 : 0);
        cpa16z(smem_u32(&Ks[stage * AT_QSZ + arow * 20 + agrp * 4]), ok ? ks : qk, ok ? 16 : 0);
    };

    prefetch(0, 0); CP_COMMIT();
    prefetch(1, 1); CP_COMMIT();

    for (int c = 0; c < NCH; c++) {
        if (c + 2 < NCH) prefetch(c + 2, (c + 2) & 3);
        CP_COMMIT();
        CP_WAIT2();
        __syncthreads();

        const float* QsS = Qs + (c & 3) * AT_QSZ;
        const float* KsS = Ks + (c & 3) * AT_QSZ;
        #pragma unroll
        for (int g = 0; g < 2; g++) {
            unsigned a[4];
            a[0] = __float_as_uint(QsS[(m0 + lr    ) * 20 + g * 8 + kc    ]);
            a[1] = __float_as_uint(QsS[(m0 + lr + 8) * 20 + g * 8 + kc    ]);
            a[2] = __float_as_uint(QsS[(m0 + lr    ) * 20 + g * 8 + kc + 4]);
            a[3] = __float_as_uint(QsS[(m0 + lr + 8) * 20 + g * 8 + kc + 4]);
            #pragma unroll
            for (int j = 0; j < 4; j++) {
                unsigned b[2];
                b[0] = __float_as_uint(KsS[(nb0 + 8 * j + lr) * 20 + g * 8 + kc    ]);
                b[1] = __float_as_uint(KsS[(nb0 + 8 * j + lr) * 20 + g * 8 + kc + 4]);
                mma8(acc[j], a, b);
            }
        }
    }

    float* pb = part + (((size_t)z * Nn + n) * Hh + hh) * 4096;
    #pragma unroll
    for (int half = 0; half < 2; half++) {
        int t = m0 + lr + half * 8;
        #pragma unroll
        for (int j = 0; j < 4; j++) {
            int q = nb0 + 8 * j + 2 * kc;
            *(float2*)(pb + (size_t)t * 64 + q) =
                make_float2(acc[j][half * 2], acc[j][half * 2 + 1]);
        }
    }
}

__global__ void attn_combine_kernel(const float* __restrict__ part,
                                    const float* __restrict__ alphas,
                                    const float* __restrict__ att1s,
                                    float* __restrict__ att)
{
    int idx = blockIdx.x * blockDim.x + threadIdx.x;
    const int total = Nn * Hh * Tt * Tt;
    if (idx >= total) return;
    int tq = idx & (Tt * Tt - 1);
    int h  = (idx / (Tt * Tt)) % Hh;
    float p = part[idx] + part[(size_t)total + idx]
            + part[2 * (size_t)total + idx] + part[3 * (size_t)total + idx];
    const float inv = 1.0f / (float)(QKd * Vv);
    att[idx] = rna_f(tanhf(p * inv) * alphas[h] + att1s[(size_t)h * Tt * Tt + tq]);
}

// ============================================================================
// z_mma: z[n,c,q,v] = leaky(bn_c(sum_{s,t} G2[n,s,c,t,v]*att[n,s,t,q]) + g)
// 512 threads, 16 warps = 4(M)x4(N). M=64(q), N=224(v pad), K=192 (12 chunks).
// ============================================================================
#define ZM_ASZ (16 * 72)
#define ZM_BSZ (16 * 232)
#define ZM_SMEM (4 * (ZM_ASZ + ZM_BSZ) * 4)

__global__ __launch_bounds__(512, 2)
void z_mma(const float* __restrict__ G2, const float* __restrict__ att,
           const float* __restrict__ g,
           const float* __restrict__ on_b, const float* __restrict__ on_g,
           const float* __restrict__ on_bb, const float* __restrict__ on_m,
           const float* __restrict__ on_v,
           float* __restrict__ out)
{
    extern __shared__ float sm[];
    float* As = sm;                 // 4 stages [t=16][q=64 pad 72]  att
    float* Bs = sm + 4 * ZM_ASZ;    // 4 stages [t=16][v=224 pad 232] G2

    const int cch = blockIdx.x, n = blockIdx.y;
    const int tid = threadIdx.x, lane = tid & 31, warp = tid >> 5;
    const int wm = warp & 3, wn = warp >> 2;
    const int m0 = wm * 16, n0 = wn * 56;
    const int lr = lane >> 2, kc = lane & 3;

    float acc[7][4];
    #pragma unroll
    for (int j = 0; j < 7; j++)
        #pragma unroll
        for (int q = 0; q < 4; q++) acc[j][q] = 0.f;

    const int NCH = 12;

    auto prefetch = [&](int c, int stage) {
        int s  = c >> 2;
        int tb = (c & 3) * 16;
        const float* gb = G2 + ((size_t)n * HC + s * 64 + cch) * Pp;
        float* BsS = Bs + stage * ZM_BSZ;
        #pragma unroll
        for (int i = 0; i < 2; i++) {
            int e = tid + 512 * i;
            if (e < 896) {
                int trow = e / 56, grp = e % 56;
                int ok = (grp < 51);
                cpa16z(smem_u32(&BsS[trow * 232 + grp * 4]),
                       ok ? (gb + (size_t)(tb + trow) * 204 + grp * 4) : gb, ok ? 16 : 0);
            }
        }
        if (tid < 256) {
            float* AsS = As + stage * ZM_ASZ;
            int trow = tid >> 4, grp = tid & 15;
            cpa16(smem_u32(&AsS[trow * 72 + grp * 4]),
                  att + ((size_t)(n * Hh + s)) * 4096 + (size_t)(tb + trow) * 64 + grp * 4);
        }
    };

    prefetch(0, 0); CP_COMMIT();
    prefetch(1, 1); CP_COMMIT();

    for (int c = 0; c < NCH; c++) {
        if (c + 2 < NCH) prefetch(c + 2, (c + 2) & 3);
        CP_COMMIT();
        CP_WAIT2();
        __syncthreads();

        const float* AsS = As + (c & 3) * ZM_ASZ;
        const float* BsS = Bs + (c & 3) * ZM_BSZ;
        #pragma unroll
        for (int g8 = 0; g8 < 2; g8++) {
            unsigned a[4];
            a[0] = __float_as_uint(AsS[(g8 * 8 + kc    ) * 72 + m0 + lr    ]);
            a[1] = __float_as_uint(AsS[(g8 * 8 + kc    ) * 72 + m0 + lr + 8]);
            a[2] = __float_as_uint(AsS[(g8 * 8 + kc + 4) * 72 + m0 + lr    ]);
            a[3] = __float_as_uint(AsS[(g8 * 8 + kc + 4) * 72 + m0 + lr + 8]);
            #pragma unroll
            for (int j = 0; j < 7; j++) {
                unsigned b[2];
                b[0] = __float_as_uint(BsS[(g8 * 8 + kc    ) * 232 + n0 + 8 * j + lr]);
                b[1] = __float_as_uint(BsS[(g8 * 8 + kc + 4) * 232 + n0 + 8 * j + lr]);
                mma8(acc[j], a, b);
            }
        }
    }

    const float sbn = on_g[cch] * rsqrtf(on_v[cch] + 1e-5f);
    const float sh  = on_bb[cch] - on_m[cch] * sbn + on_b[cch] * sbn;
    const float* gres = g + ((size_t)n * Cc + cch) * Pp;
    float* zb = out + ((size_t)n * Cc + cch) * Pp;

    #pragma unroll
    for (int half = 0; half < 2; half++) {
        int q = m0 + lr + half * 8;
        #pragma unroll
        for (int j = 0; j < 7; j++) {
            int v = n0 + 8 * j + 2 * kc;
            if (v < 204) {
                float2 rv = *(const float2*)(gres + (size_t)q * 204 + v);
                float va = acc[j][half * 2]     * sbn + sh + rv.x;
                float vb = acc[j][half * 2 + 1] * sbn + sh + rv.y;
                va = (va > 0.f) ? va : 0.1f * va;
                vb = (vb > 0.f) ? vb : 0.1f * vb;
                *(float2*)(zb + (size_t)q * 204 + v) = make_float2(rna_f(va), rna_f(vb));
            }
        }
    }
}

// ---------------- launch ----------------
extern "C" void kernel_launch(void* const* d_in, const int* in_sizes, int n_in,
                              void* d_out, int out_size)
{
    const float* x      = (const float*)d_in[0];
    const float* A      = (const float*)d_in[1];
    const float* gcn_w  = (const float*)d_in[2];
    const float* gcn_b  = (const float*)d_in[3];
    const float* gcn_g  = (const float*)d_in[4];
    const float* gcn_bb = (const float*)d_in[5];
    const float* gcn_m  = (const float*)d_in[6];
    const float* gcn_v  = (const float*)d_in[7];
    const float* pe     = (const float*)d_in[8];
    const float* qkv_w  = (const float*)d_in[9];
    const float* qkv_b  = (const float*)d_in[10];
    const float* alphas = (const float*)d_in[11];
    const float* att1s  = (const float*)d_in[12];
    const float* on_w   = (const float*)d_in[13];
    const float* on_b   = (const float*)d_in[14];
    const float* on_g   = (const float*)d_in[15];
    const float* on_bb  = (const float*)d_in[16];
    const float* on_m   = (const float*)d_in[17];
    const float* on_v   = (const float*)d_in[18];
    const float* ff_w   = (const float*)d_in[19];
    const float* ff_b   = (const float*)d_in[20];
    const float* ff_g   = (const float*)d_in[21];
    const float* ff_bb  = (const float*)d_in[22];
    const float* ff_m   = (const float*)d_in[23];
    const float* ff_v   = (const float*)d_in[24];
    float* out = (float*)d_out;

    float *ph, *pg, *pqk, *pwpe, *patt, *pattp, *pG2, *pwt, *pA2;
    cudaGetSymbolAddress((void**)&ph,    d_h);
    cudaGetSymbolAddress((void**)&pg,    d_g);
    cudaGetSymbolAddress((void**)&pqk,   d_qk);
    cudaGetSymbolAddress((void**)&pwpe,  d_wpe);
    cudaGetSymbolAddress((void**)&patt,  d_att);
    cudaGetSymbolAddress((void**)&pattp, d_attp);
    cudaGetSymbolAddress((void**)&pG2,   d_G2);
    cudaGetSymbolAddress((void**)&pwt,   d_wt);
    cudaGetSymbolAddress((void**)&pA2,   d_A2);

    static int attr_set = 0;
    if (!attr_set) {
        cudaFuncSetAttribute(conv_mma<MODE_BIAS, 0>, cudaFuncAttributeMaxDynamicSharedMemorySize, CV_SMEM);
        cudaFuncSetAttribute(conv_mma<MODE_BIAS, 1>, cudaFuncAttributeMaxDynamicSharedMemorySize, CV_SMEM);
        cudaFuncSetAttribute(conv_mma<MODE_ADD2D, 1>, cudaFuncAttributeMaxDynamicSharedMemorySize, CV_SMEM);
        cudaFuncSetAttribute(conv_mma<MODE_NONE, 1>, cudaFuncAttributeMaxDynamicSharedMemorySize, CV_SMEM);
        cudaFuncSetAttribute(conv_mma<MODE_BN_RES_LEAKY, 0>, cudaFuncAttributeMaxDynamicSharedMemorySize, CV_SMEM);
        cudaFuncSetAttribute(adj_mma, cudaFuncAttributeMaxDynamicSharedMemorySize, AD_SMEM);
        cudaFuncSetAttribute(attn_mma, cudaFuncAttributeMaxDynamicSharedMemorySize, AT_SMEM);
        cudaFuncSetAttribute(z_mma, cudaFuncAttributeMaxDynamicSharedMemorySize, ZM_SMEM);
        attr_set = 1;
    }

    dim3 blk5(512), blk2(256);

    // P0: tf32 pre-convert small operands
    prep_kernel<<<(4096 + 6144 + 4096 + 12288 + 224 * 208 + 255) / 256, blk2>>>(
        gcn_w, qkv_w, ff_w, on_w, A, pwt, pA2);

    // K0: wpe = qkv_w @ pe + qkv_b
    conv_mma<MODE_BIAS, 0><<<dim3(Pp / 256, 2, 1), blk5, CV_SMEM>>>(
        pe, pwt + WT_QKV, qkv_b, nullptr, nullptr, nullptr, nullptr, nullptr, nullptr,
        pwpe, Cc, OQKV);

    // K1: h = gcn conv
    conv_mma<MODE_BIAS, 1><<<dim3(Pp / 256, 1, Nn), blk5, CV_SMEM>>>(
        x, pwt + WT_GCN, gcn_b, nullptr, nullptr, nullptr, nullptr, nullptr, nullptr,
        ph, Cc, Cc);

    // K2: g = relu(bn(A @ h) + x)
    adj_mma<<<dim3((Nn * Cc * Tt) / 64, 1, 1), blk5, AD_SMEM>>>(
        ph, pA2, x, gcn_g, gcn_bb, gcn_m, gcn_v, pg);

    // K3: qk = qkv_w @ g + wpe
    conv_mma<MODE_ADD2D, 1><<<dim3(Pp / 256, 2, Nn), blk5, CV_SMEM>>>(
        pg, pwt + WT_QKV, nullptr, pwpe, nullptr, nullptr, nullptr, nullptr, nullptr,
        pqk, Cc, OQKV);

    // K4: attention scores + combine
    attn_mma<<<dim3(Hh, Nn, 4), blk2, AT_SMEM>>>(pqk, pattp);
    attn_combine_kernel<<<(Nn * Hh * Tt * Tt + 255) / 256, blk2>>>(pattp, alphas, att1s, patt);

    // K5: G2 = W2 @ g
    conv_mma<MODE_NONE, 1><<<dim3(Pp / 256, 3, Nn), blk5, CV_SMEM>>>(
        pg, pwt + WT_W2, nullptr, nullptr, nullptr, nullptr, nullptr, nullptr, nullptr,
        pG2, Cc, HC);

    // K6: z = leaky(bn(sum G2*att + on_b) + g) -> d_h
    z_mma<<<dim3(Cc, Nn), blk5, ZM_SMEM>>>(
        pG2, patt, pg, on_b, on_g, on_bb, on_m, on_v, ph);

    // K7: out = leaky(bn(ff_w @ z + ff_b) + g)
    conv_mma<MODE_BN_RES_LEAKY, 0><<<dim3(Pp / 256, 1, Nn), blk5, CV_SMEM>>>(
        ph, pwt + WT_FF, ff_b, nullptr, pg, ff_g, ff_bb, ff_m, ff_v,
        out, Cc, Cc);
}

// round 7
// speedup vs baseline: 1.0189x; 1.0189x over previous
#include <cuda_runtime.h>
#include <math.h>
#include <stdint.h>

// Problem constants
#define Nn   32
#define Cc   64
#define Tt   64
#define Vv   204
#define Hh   3
#define QKd  16
#define Pp   13056
#define OQKV 96
#define HC   192

// ---------------- scratch ----------------
__device__ float d_h   [(size_t)Nn * Cc * Pp + 64];   // gcn conv out; later z
__device__ float d_g   [(size_t)Nn * Cc * Pp + 64];
__device__ float d_qk  [(size_t)Nn * OQKV * Pp + 64];
__device__ float d_wpe [(size_t)OQKV * Pp];
__device__ float d_att [(size_t)Nn * Hh * Tt * Tt];
__device__ float d_attp[(size_t)4 * Nn * Hh * Tt * Tt];
__device__ float d_G2  [(size_t)Nn * HC * Pp + 64];
__device__ float d_wf  [28672];        // fragment-packed tf32 weights: gcn|qkv|ff|w2
__device__ float d_A2  [208 * 208];    // tf32 zero-padded adjacency [u][v]

#define WF_GCN 0
#define WF_QKV 4096
#define WF_FF  12288
#define WF_W2  16384

enum { MODE_BIAS = 0, MODE_ADD2D = 1, MODE_BN_RES_LEAKY = 2, MODE_NONE = 3 };

// ---------------- helpers ----------------
__device__ __forceinline__ unsigned cvt_tf32(float f) {
    unsigned u;
    asm("cvt.rna.tf32.f32 %0, %1;" : "=r"(u) : "f"(f));
    return u;
}
__device__ __forceinline__ float rna_f(float f) { return __uint_as_float(cvt_tf32(f)); }

__device__ __forceinline__ void mma8(float* d, const unsigned* a, const unsigned* b) {
    asm volatile(
        "mma.sync.aligned.m16n8k8.row.col.f32.tf32.tf32.f32 "
        "{%0,%1,%2,%3},{%4,%5,%6,%7},{%8,%9},{%0,%1,%2,%3};"
        : "+f"(d[0]), "+f"(d[1]), "+f"(d[2]), "+f"(d[3])
        : "r"(a[0]), "r"(a[1]), "r"(a[2]), "r"(a[3]), "r"(b[0]), "r"(b[1]));
}

__device__ __forceinline__ uint32_t smem_u32(const void* p) {
    return (uint32_t)__cvta_generic_to_shared(p);
}
__device__ __forceinline__ void cpa16(uint32_t dst, const void* src) {
    asm volatile("cp.async.cg.shared.global [%0],[%1],16;" :: "r"(dst), "l"(src));
}
__device__ __forceinline__ void cpa16z(uint32_t dst, const void* src, int sz) {
    asm volatile("cp.async.cg.shared.global [%0],[%1],16,%2;" :: "r"(dst), "l"(src), "r"(sz));
}
#define CP_COMMIT() asm volatile("cp.async.commit_group;")
#define CP_WAIT2()  asm volatile("cp.async.wait_group 2;")

// ============================================================================
// prep: pack weights into mma-fragment layout (tf32) + pad adjacency.
// Frag layout per matrix: [mblk(32 rows)][chunk(16 k)][lane(32)][16 floats]
// 16 floats = [f(2)][g(2)][e(4)]: row = mblk*32+f*16+(lane>>2)+(e&1)*8,
//                                 col = chunk*16+g*8+(lane&3)+(e>>1)*4
// ============================================================================
__global__ void prep_kernel(const float* __restrict__ gcn_w, const float* __restrict__ qkv_w,
                            const float* __restrict__ ff_w, const float* __restrict__ on_w,
                            const float* __restrict__ A,
                            float* __restrict__ wf, float* __restrict__ A2)
{
    int i = blockIdx.x * 256 + threadIdx.x;
    if (i < 28672) {
        const float* W; int Oc; int base; int isw2 = 0;
        if (i < 4096)       { base = WF_GCN; W = gcn_w; Oc = 64; }
        else if (i < 12288) { base = WF_QKV; W = qkv_w; Oc = 96; }
        else if (i < 16384) { base = WF_FF;  W = ff_w;  Oc = 64; }
        else                { base = WF_W2;  W = on_w;  Oc = 192; isw2 = 1; }
        int local = i - base;
        int e4   = local & 15;
        int lane = (local >> 4) & 31;
        int c    = (local >> 9) & 3;
        int mblk = local >> 11;
        int f = e4 >> 3, gg = (e4 >> 2) & 1, e = e4 & 3;
        int row = mblk * 32 + f * 16 + (lane >> 2) + (e & 1) * 8;
        int col = c * 16 + gg * 8 + (lane & 3) + (e >> 1) * 4;
        float v = 0.f;
        if (row < Oc)
            v = isw2 ? on_w[(size_t)(row & 63) * HC + (row >> 6) * 64 + col]
                     : W[(size_t)row * 64 + col];
        wf[i] = rna_f(v);
        return;
    }
    i -= 28672;
    if (i < 208 * 208) {
        int u = i / 208, v = i % 208;
        A2[i] = (u < 204 && v < 204) ? rna_f(A[(size_t)u * 204 + v]) : 0.f;
    }
}

// ============================================================================
// conv_mma: out[n,o,p] = sum_c W[o,c]*in[n,c,p], Kc=64 always.
// CTA: 256 thr, 8 warps = 2(M)x4(N). Tile M=64, N=192, k-chunk 16 (4 chunks).
// A operand from fragment-packed global (L1-resident); B via 4-stage cp.async.
// ============================================================================
#define CV_BST 200                       // B row stride (200 % 32 == 8: conflict-free)
#define CV_BSZ (16 * CV_BST)
#define CV_SMEM (4 * CV_BSZ * 4)

template <int MODE, int ROUND>
__global__ __launch_bounds__(256, 3)
void conv_mma(const float* __restrict__ in, const float* __restrict__ Wfrag,
              const float* __restrict__ bias, const float* __restrict__ add2d,
              const float* __restrict__ res,
              const float* __restrict__ bng, const float* __restrict__ bnb,
              const float* __restrict__ bnm, const float* __restrict__ bnv,
              float* __restrict__ out, int Oc)
{
    extern __shared__ float sm[];   // 4 stages of [16][CV_BST]

    const int n  = blockIdx.z;
    const int pt = blockIdx.x * 192;
    const int ot = blockIdx.y * 64;
    const int tid = threadIdx.x, lane = tid & 31, warp = tid >> 5;
    const int wm = warp & 1, wn = warp >> 1;
    const int m0 = wm * 32, n0 = wn * 48;
    const int lr = lane >> 2, kc = lane & 3;
    const int mblk = (ot >> 5) + wm;

    const float* inN = in + (size_t)n * 64 * Pp + pt;

    float acc[2][6][4];
    #pragma unroll
    for (int f = 0; f < 2; f++)
        #pragma unroll
        for (int j = 0; j < 6; j++)
            #pragma unroll
            for (int q = 0; q < 4; q++) acc[f][j][q] = 0.f;

    auto prefetch = [&](int c, int stage) {
        float* BsS = sm + stage * CV_BSZ;
        const float* bsrc = inN + (size_t)(c * 16) * Pp;
        #pragma unroll
        for (int i = 0; i < 3; i++) {
            int e = tid + 256 * i;          // 0..767
            int k = e / 48, grp = e % 48;
            cpa16(smem_u32(&BsS[k * CV_BST + grp * 4]), bsrc + (size_t)k * Pp + grp * 4);
        }
    };

    prefetch(0, 0); CP_COMMIT();
    prefetch(1, 1); CP_COMMIT();

    #pragma unroll
    for (int c = 0; c < 4; c++) {
        if (c + 2 < 4) prefetch(c + 2, c + 2);
        CP_COMMIT();
        CP_WAIT2();
        __syncthreads();

        const float* BsS = sm + c * CV_BSZ;
        const float4* wfp = (const float4*)(Wfrag + ((size_t)(mblk * 4 + c) * 32 + lane) * 16);
        #pragma unroll
        for (int g = 0; g < 2; g++) {
            unsigned b[6][2];
            #pragma unroll
            for (int j = 0; j < 6; j++) {
                b[j][0] = __float_as_uint(BsS[(g * 8 + kc    ) * CV_BST + n0 + 8 * j + lr]);
                b[j][1] = __float_as_uint(BsS[(g * 8 + kc + 4) * CV_BST + n0 + 8 * j + lr]);
            }
            float4 af0 = wfp[g];        // f=0
            float4 af1 = wfp[2 + g];    // f=1
            unsigned a0[4] = {__float_as_uint(af0.x), __float_as_uint(af0.y),
                              __float_as_uint(af0.z), __float_as_uint(af0.w)};
            unsigned a1[4] = {__float_as_uint(af1.x), __float_as_uint(af1.y),
                              __float_as_uint(af1.z), __float_as_uint(af1.w)};
            #pragma unroll
            for (int j = 0; j < 6; j++) {
                mma8(acc[0][j], a0, b[j]);
                mma8(acc[1][j], a1, b[j]);
            }
        }
    }

    #pragma unroll
    for (int f = 0; f < 2; f++) {
        #pragma unroll
        for (int half = 0; half < 2; half++) {
            int o = ot + m0 + f * 16 + lr + half * 8;
            if (o >= Oc) continue;
            size_t obase = ((size_t)n * Oc + o) * Pp;
            if (MODE == MODE_NONE) {
                #pragma unroll
                for (int j = 0; j < 6; j++) {
                    int p = pt + n0 + 8 * j + 2 * kc;
                    float va = acc[f][j][half * 2], vb = acc[f][j][half * 2 + 1];
                    if (ROUND) { va = rna_f(va); vb = rna_f(vb); }
                    *(float2*)(out + obase + p) = make_float2(va, vb);
                }
            } else if (MODE == MODE_BIAS) {
                float b = bias[o];
                #pragma unroll
                for (int j = 0; j < 6; j++) {
                    int p = pt + n0 + 8 * j + 2 * kc;
                    float va = acc[f][j][half * 2] + b, vb = acc[f][j][half * 2 + 1] + b;
                    if (ROUND) { va = rna_f(va); vb = rna_f(vb); }
                    *(float2*)(out + obase + p) = make_float2(va, vb);
                }
            } else if (MODE == MODE_ADD2D) {
                size_t abase = (size_t)o * Pp;
                #pragma unroll
                for (int j = 0; j < 6; j++) {
                    int p = pt + n0 + 8 * j + 2 * kc;
                    float2 av = *(const float2*)(add2d + abase + p);
                    float va = acc[f][j][half * 2] + av.x, vb = acc[f][j][half * 2 + 1] + av.y;
                    if (ROUND) { va = rna_f(va); vb = rna_f(vb); }
                    *(float2*)(out + obase + p) = make_float2(va, vb);
                }
            } else { // MODE_BN_RES_LEAKY
                float s  = bng[o] * rsqrtf(bnv[o] + 1e-5f);
                float sh = bnb[o] - bnm[o] * s + bias[o] * s;
                #pragma unroll
                for (int j = 0; j < 6; j++) {
                    int p = pt + n0 + 8 * j + 2 * kc;
                    float2 rv = *(const float2*)(res + obase + p);
                    float va = acc[f][j][half * 2]     * s + sh + rv.x;
                    float vb = acc[f][j][half * 2 + 1] * s + sh + rv.y;
                    va = (va > 0.f) ? va : 0.1f * va;
                    vb = (vb > 0.f) ? vb : 0.1f * vb;
                    if (ROUND) { va = rna_f(va); vb = rna_f(vb); }
                    *(float2*)(out + obase + p) = make_float2(va, vb);
                }
            }
        }
    }
}

// ============================================================================
// adj_mma (R5 verbatim): g[r,u] = relu(bn_c(sum_v h[r,v]*A2[u,v]) + x[r,u])
// M=64(r), N=208(u), K=208 padded (13 chunks), 4-stage ring, 256 thr.
// ============================================================================
#define AD_ASZ (64 * 20)
#define AD_BSZ (208 * 20)
#define AD_SMEM (4 * (AD_ASZ + AD_BSZ) * 4)

__global__ __launch_bounds__(256, 2)
void adj_mma(const float* __restrict__ h, const float* __restrict__ A2,
             const float* __restrict__ x,
             const float* __restrict__ bng, const float* __restrict__ bnb,
             const float* __restrict__ bnm, const float* __restrict__ bnv,
             float* __restrict__ out)
{
    extern __shared__ float sm[];
    float* As = sm;
    float* Bs = sm + 4 * AD_ASZ;

    const int rt = blockIdx.x * 64;
    const int tid = threadIdx.x, lane = tid & 31, warp = tid >> 5;
    const int wm = warp & 3, wn = warp >> 2;
    const int m0 = wm * 16, nb0 = wn * 104;
    const int lr = lane >> 2, kc = lane & 3;

    const int ch  = (rt >> 6) & 63;
    const float s  = bng[ch] * rsqrtf(bnv[ch] + 1e-5f);
    const float sh = bnb[ch] - bnm[ch] * s;

    float acc[13][4];
    #pragma unroll
    for (int j = 0; j < 13; j++)
        #pragma unroll
        for (int q = 0; q < 4; q++) acc[j][q] = 0.f;

    const int arow = tid >> 2, agrp = tid & 3;
    const int NCH = 13;

    auto prefetch = [&](int c, int stage) {
        float* BsS = Bs + stage * AD_BSZ;
        #pragma unroll
        for (int i = 0; i < 4; i++) {
            int e = tid + 256 * i;
            if (e < 832) {
                int u = e >> 2, grp = e & 3;
                cpa16(smem_u32(&BsS[u * 20 + grp * 4]), A2 + (size_t)u * 208 + c * 16 + grp * 4);
            }
        }
        float* AsS = As + stage * AD_ASZ;
        cpa16(smem_u32(&AsS[arow * 20 + agrp * 4]),
              h + (size_t)(rt + arow) * 204 + c * 16 + agrp * 4);  // over-read x zero B cols
    };

    prefetch(0, 0); CP_COMMIT();
    prefetch(1, 1); CP_COMMIT();

    for (int c = 0; c < NCH; c++) {
        if (c + 2 < NCH) prefetch(c + 2, (c + 2) & 3);
        CP_COMMIT();
        CP_WAIT2();
        __syncthreads();

        const float* AsS = As + (c & 3) * AD_ASZ;
        const float* BsS = Bs + (c & 3) * AD_BSZ;
        #pragma unroll
        for (int g = 0; g < 2; g++) {
            unsigned a[4];
            a[0] = __float_as_uint(AsS[(m0 + lr    ) * 20 + g * 8 + kc    ]);
            a[1] = __float_as_uint(AsS[(m0 + lr + 8) * 20 + g * 8 + kc    ]);
            a[2] = __float_as_uint(AsS[(m0 + lr    ) * 20 + g * 8 + kc + 4]);
            a[3] = __float_as_uint(AsS[(m0 + lr + 8) * 20 + g * 8 + kc + 4]);
            #pragma unroll
            for (int j = 0; j < 13; j++) {
                unsigned b[2];
                b[0] = __float_as_uint(BsS[(nb0 + 8 * j + lr) * 20 + g * 8 + kc    ]);
                b[1] = __float_as_uint(BsS[(nb0 + 8 * j + lr) * 20 + g * 8 + kc + 4]);
                mma8(acc[j], a, b);
            }
        }
    }

    #pragma unroll
    for (int half = 0; half < 2; half++) {
        int r = rt + m0 + lr + half * 8;
        size_t rbase = (size_t)r * 204;
        #pragma unroll
        for (int j = 0; j < 13; j++) {
            int u = nb0 + 8 * j + 2 * kc;
            if (u < 204) {
                float2 xv = *(const float2*)(x + rbase + u);
                float va = acc[j][half * 2]     * s + sh + xv.x;
                float vb = acc[j][half * 2 + 1] * s + sh + xv.y;
                *(float2*)(out + rbase + u) =
                    make_float2(rna_f(fmaxf(va, 0.f)), rna_f(fmaxf(vb, 0.f)));
            }
        }
    }
}

// ============================================================================
// attn_mma: part[z,n,h,t,q] = sum_{c in 4-chunk z, v} q[c,t,v]*k[c,q,v] (tf32)
// ============================================================================
#define AT_QSZ (64 * 20)
#define AT_SMEM (4 * 2 * AT_QSZ * 4)

__global__ __launch_bounds__(256, 4)
void attn_mma(const float* __restrict__ qk, float* __restrict__ part)
{
    extern __shared__ float sm[];
    float* Qs = sm;
    float* Ks = sm + 4 * AT_QSZ;

    const int hh = blockIdx.x, n = blockIdx.y, z = blockIdx.z;
    const int cc0 = z * 4;
    const int tid = threadIdx.x, lane = tid & 31, warp = tid >> 5;
    const int wm = warp & 3, wn = warp >> 2;
    const int m0 = wm * 16, nb0 = wn * 32;
    const int lr = lane >> 2, kc = lane & 3;

    const float* qbase = qk + ((size_t)n * OQKV + hh * QKd) * Pp;
    const float* kbase = qk + ((size_t)n * OQKV + Hh * QKd + hh * QKd) * Pp;

    const int arow = tid >> 2, agrp = tid & 3;
    const int NCH = 52;

    float acc[4][4];
    #pragma unroll
    for (int j = 0; j < 4; j++)
        #pragma unroll
        for (int q = 0; q < 4; q++) acc[j][q] = 0.f;

    auto prefetch = [&](int c, int stage) {
        int ci = cc0 + (c / 13);
        int vb = (c % 13) * 16;
        int v = vb + agrp * 4;
        int ok = (v < 204);
        const float* qs = qbase + (size_t)ci * Pp + (size_t)arow * 204 + v;
        const float* ks = kbase + (size_t)ci * Pp + (size_t)arow * 204 + v;
        cpa16z(smem_u32(&Qs[stage * AT_QSZ + arow * 20 + agrp * 4]), ok ? qs : qk, ok ? 16 : 0);
        cpa16z(smem_u32(&Ks[stage * AT_QSZ + arow * 20 + agrp * 4]), ok ? ks : qk, ok ? 16 : 0);
    };

    prefetch(0, 0); CP_COMMIT();
    prefetch(1, 1); CP_COMMIT();

    for (int c = 0; c < NCH; c++) {
        if (c + 2 < NCH) prefetch(c + 2, (c + 2) & 3);
        CP_COMMIT();
        CP_WAIT2();
        __syncthreads();

        const float* QsS = Qs + (c & 3) * AT_QSZ;
        const float* KsS = Ks + (c & 3) * AT_QSZ;
        #pragma unroll
        for (int g = 0; g < 2; g++) {
            unsigned a[4];
            a[0] = __float_as_uint(QsS[(m0 + lr    ) * 20 + g * 8 + kc    ]);
            a[1] = __float_as_uint(QsS[(m0 + lr + 8) * 20 + g * 8 + kc    ]);
            a[2] = __float_as_uint(QsS[(m0 + lr    ) * 20 + g * 8 + kc + 4]);
            a[3] = __float_as_uint(QsS[(m0 + lr + 8) * 20 + g * 8 + kc + 4]);
            #pragma unroll
            for (int j = 0; j < 4; j++) {
                unsigned b[2];
                b[0] = __float_as_uint(KsS[(nb0 + 8 * j + lr) * 20 + g * 8 + kc    ]);
                b[1] = __float_as_uint(KsS[(nb0 + 8 * j + lr) * 20 + g * 8 + kc + 4]);
                mma8(acc[j], a, b);
            }
        }
    }

    float* pb = part + (((size_t)z * Nn + n) * Hh + hh) * 4096;
    #pragma unroll
    for (int half = 0; half < 2; half++) {
        int t = m0 + lr + half * 8;
        #pragma unroll
        for (int j = 0; j < 4; j++) {
            int q = nb0 + 8 * j + 2 * kc;
            *(float2*)(pb + (size_t)t * 64 + q) =
                make_float2(acc[j][half * 2], acc[j][half * 2 + 1]);
        }
    }
}

__global__ void attn_combine_kernel(const float* __restrict__ part,
                                    const float* __restrict__ alphas,
                                    const float* __restrict__ att1s,
                                    float* __restrict__ att)
{
    int idx = blockIdx.x * blockDim.x + threadIdx.x;
    const int total = Nn * Hh * Tt * Tt;
    if (idx >= total) return;
    int tq = idx & (Tt * Tt - 1);
    int h  = (idx / (Tt * Tt)) % Hh;
    float p = part[idx] + part[(size_t)total + idx]
            + part[2 * (size_t)total + idx] + part[3 * (size_t)total + idx];
    const float inv = 1.0f / (float)(QKd * Vv);
    att[idx] = rna_f(tanhf(p * inv) * alphas[h] + att1s[(size_t)h * Tt * Tt + tq]);
}

// ============================================================================
// z_mma (R5 tiling, conflict-free B stride 232):
// z[n,c,q,v] = leaky(bn_c(sum_{s,t} G2[n,s,c,t,v]*att[n,s,t,q]) + g)
// ============================================================================
#define ZM_ASZ (16 * 72)
#define ZM_BST 232
#define ZM_BSZ (16 * ZM_BST)
#define ZM_SMEM (4 * (ZM_ASZ + ZM_BSZ) * 4)

__global__ __launch_bounds__(256, 2)
void z_mma(const float* __restrict__ G2, const float* __restrict__ att,
           const float* __restrict__ g,
           const float* __restrict__ on_b, const float* __restrict__ on_g,
           const float* __restrict__ on_bb, const float* __restrict__ on_m,
           const float* __restrict__ on_v,
           float* __restrict__ out)
{
    extern __shared__ float sm[];
    float* As = sm;                 // 4 stages [t=16][q=64 pad 72]
    float* Bs = sm + 4 * ZM_ASZ;    // 4 stages [t=16][v pad ZM_BST]

    const int cch = blockIdx.x, n = blockIdx.y;
    const int tid = threadIdx.x, lane = tid & 31, warp = tid >> 5;
    const int wm = warp & 3, wn = warp >> 2;
    const int m0 = wm * 16, nb0 = wn * 104;
    const int lr = lane >> 2, kc = lane & 3;

    float acc[13][4];
    #pragma unroll
    for (int j = 0; j < 13; j++)
        #pragma unroll
        for (int q = 0; q < 4; q++) acc[j][q] = 0.f;

    const int NCH = 12;

    auto prefetch = [&](int c, int stage) {
        int s  = c >> 2;
        int tb = (c & 3) * 16;
        const float* gb = G2 + ((size_t)n * HC + s * 64 + cch) * Pp;
        float* BsS = Bs + stage * ZM_BSZ;
        #pragma unroll
        for (int i = 0; i < 4; i++) {
            int e = tid + 256 * i;
            if (e < 832) {
                int trow = e / 52, grp = e % 52;
                int ok = (grp < 51);
                cpa16z(smem_u32(&BsS[trow * ZM_BST + grp * 4]),
                       ok ? (gb + (size_t)(tb + trow) * 204 + grp * 4) : gb, ok ? 16 : 0);
            }
        }
        float* AsS = As + stage * ZM_ASZ;
        int trow = tid >> 4, grp = tid & 15;
        cpa16(smem_u32(&AsS[trow * 72 + grp * 4]),
              att + ((size_t)(n * Hh + s)) * 4096 + (size_t)(tb + trow) * 64 + grp * 4);
    };

    prefetch(0, 0); CP_COMMIT();
    prefetch(1, 1); CP_COMMIT();

    for (int c = 0; c < NCH; c++) {
        if (c + 2 < NCH) prefetch(c + 2, (c + 2) & 3);
        CP_COMMIT();
        CP_WAIT2();
        __syncthreads();

        const float* AsS = As + (c & 3) * ZM_ASZ;
        const float* BsS = Bs + (c & 3) * ZM_BSZ;
        #pragma unroll
        for (int g8 = 0; g8 < 2; g8++) {
            unsigned a[4];
            a[0] = __float_as_uint(AsS[(g8 * 8 + kc    ) * 72 + m0 + lr    ]);
            a[1] = __float_as_uint(AsS[(g8 * 8 + kc    ) * 72 + m0 + lr + 8]);
            a[2] = __float_as_uint(AsS[(g8 * 8 + kc + 4) * 72 + m0 + lr    ]);
            a[3] = __float_as_uint(AsS[(g8 * 8 + kc + 4) * 72 + m0 + lr + 8]);
            #pragma unroll
            for (int j = 0; j < 13; j++) {
                unsigned b[2];
                b[0] = __float_as_uint(BsS[(g8 * 8 + kc    ) * ZM_BST + nb0 + 8 * j + lr]);
                b[1] = __float_as_uint(BsS[(g8 * 8 + kc + 4) * ZM_BST + nb0 + 8 * j + lr]);
                mma8(acc[j], a, b);
            }
        }
    }

    const float sbn = on_g[cch] * rsqrtf(on_v[cch] + 1e-5f);
    const float sh  = on_bb[cch] - on_m[cch] * sbn + on_b[cch] * sbn;
    const float* gres = g + ((size_t)n * Cc + cch) * Pp;
    float* zb = out + ((size_t)n * Cc + cch) * Pp;

    #pragma unroll
    for (int half = 0; half < 2; half++) {
        int q = m0 + lr + half * 8;
        #pragma unroll
        for (int j = 0; j < 13; j++) {
            int v = nb0 + 8 * j + 2 * kc;
            if (v < 204) {
                float2 rv = *(const float2*)(gres + (size_t)q * 204 + v);
                float va = acc[j][half * 2]     * sbn + sh + rv.x;
                float vb = acc[j][half * 2 + 1] * sbn + sh + rv.y;
                va = (va > 0.f) ? va : 0.1f * va;
                vb = (vb > 0.f) ? vb : 0.1f * vb;
                *(float2*)(zb + (size_t)q * 204 + v) = make_float2(rna_f(va), rna_f(vb));
            }
        }
    }
}

// ---------------- launch ----------------
extern "C" void kernel_launch(void* const* d_in, const int* in_sizes, int n_in,
                              void* d_out, int out_size)
{
    const float* x      = (const float*)d_in[0];
    const float* A      = (const float*)d_in[1];
    const float* gcn_w  = (const float*)d_in[2];
    const float* gcn_b  = (const float*)d_in[3];
    const float* gcn_g  = (const float*)d_in[4];
    const float* gcn_bb = (const float*)d_in[5];
    const float* gcn_m  = (const float*)d_in[6];
    const float* gcn_v  = (const float*)d_in[7];
    const float* pe     = (const float*)d_in[8];
    const float* qkv_w  = (const float*)d_in[9];
    const float* qkv_b  = (const float*)d_in[10];
    const float* alphas = (const float*)d_in[11];
    const float* att1s  = (const float*)d_in[12];
    const float* on_w   = (const float*)d_in[13];
    const float* on_b   = (const float*)d_in[14];
    const float* on_g   = (const float*)d_in[15];
    const float* on_bb  = (const float*)d_in[16];
    const float* on_m   = (const float*)d_in[17];
    const float* on_v   = (const float*)d_in[18];
    const float* ff_w   = (const float*)d_in[19];
    const float* ff_b   = (const float*)d_in[20];
    const float* ff_g   = (const float*)d_in[21];
    const float* ff_bb  = (const float*)d_in[22];
    const float* ff_m   = (const float*)d_in[23];
    const float* ff_v   = (const float*)d_in[24];
    float* out = (float*)d_out;

    float *ph, *pg, *pqk, *pwpe, *patt, *pattp, *pG2, *pwf, *pA2;
    cudaGetSymbolAddress((void**)&ph,    d_h);
    cudaGetSymbolAddress((void**)&pg,    d_g);
    cudaGetSymbolAddress((void**)&pqk,   d_qk);
    cudaGetSymbolAddress((void**)&pwpe,  d_wpe);
    cudaGetSymbolAddress((void**)&patt,  d_att);
    cudaGetSymbolAddress((void**)&pattp, d_attp);
    cudaGetSymbolAddress((void**)&pG2,   d_G2);
    cudaGetSymbolAddress((void**)&pwf,   d_wf);
    cudaGetSymbolAddress((void**)&pA2,   d_A2);

    static int attr_set = 0;
    if (!attr_set) {
        cudaFuncSetAttribute(conv_mma<MODE_BIAS, 0>, cudaFuncAttributeMaxDynamicSharedMemorySize, CV_SMEM);
        cudaFuncSetAttribute(conv_mma<MODE_BIAS, 1>, cudaFuncAttributeMaxDynamicSharedMemorySize, CV_SMEM);
        cudaFuncSetAttribute(conv_mma<MODE_ADD2D, 1>, cudaFuncAttributeMaxDynamicSharedMemorySize, CV_SMEM);
        cudaFuncSetAttribute(conv_mma<MODE_NONE, 1>, cudaFuncAttributeMaxDynamicSharedMemorySize, CV_SMEM);
        cudaFuncSetAttribute(conv_mma<MODE_BN_RES_LEAKY, 0>, cudaFuncAttributeMaxDynamicSharedMemorySize, CV_SMEM);
        cudaFuncSetAttribute(adj_mma, cudaFuncAttributeMaxDynamicSharedMemorySize, AD_SMEM);
        cudaFuncSetAttribute(attn_mma, cudaFuncAttributeMaxDynamicSharedMemorySize, AT_SMEM);
        cudaFuncSetAttribute(z_mma, cudaFuncAttributeMaxDynamicSharedMemorySize, ZM_SMEM);
        attr_set = 1;
    }

    dim3 blk(256);
    const int PT = Pp / 192;   // 68 p-tiles

    // P0: pack weights into fragment layout + pad adjacency (tf32)
    prep_kernel<<<(28672 + 208 * 208 + 255) / 256, blk>>>(
        gcn_w, qkv_w, ff_w, on_w, A, pwf, pA2);

    // K0: wpe = qkv_w @ pe + qkv_b
    conv_mma<MODE_BIAS, 0><<<dim3(PT, 2, 1), blk, CV_SMEM>>>(
        pe, pwf + WF_QKV, qkv_b, nullptr, nullptr, nullptr, nullptr, nullptr, nullptr,
        pwpe, OQKV);

    // K1: h = gcn conv (tf32-rounded at store)
    conv_mma<MODE_BIAS, 1><<<dim3(PT, 1, Nn), blk, CV_SMEM>>>(
        x, pwf + WF_GCN, gcn_b, nullptr, nullptr, nullptr, nullptr, nullptr, nullptr,
        ph, Cc);

    // K2: g = relu(bn(A @ h) + x)
    adj_mma<<<dim3((Nn * Cc * Tt) / 64, 1, 1), blk, AD_SMEM>>>(
        ph, pA2, x, gcn_g, gcn_bb, gcn_m, gcn_v, pg);

    // K3: qk = qkv_w @ g + wpe (rounded)
    conv_mma<MODE_ADD2D, 1><<<dim3(PT, 2, Nn), blk, CV_SMEM>>>(
        pg, pwf + WF_QKV, nullptr, pwpe, nullptr, nullptr, nullptr, nullptr, nullptr,
        pqk, OQKV);

    // K4: attention scores + combine
    attn_mma<<<dim3(Hh, Nn, 4), blk, AT_SMEM>>>(pqk, pattp);
    attn_combine_kernel<<<(Nn * Hh * Tt * Tt + 255) / 256, blk>>>(pattp, alphas, att1s, patt);

    // K5: G2 = W2 @ g (rounded)
    conv_mma<MODE_NONE, 1><<<dim3(PT, 3, Nn), blk, CV_SMEM>>>(
        pg, pwf + WF_W2, nullptr, nullptr, nullptr, nullptr, nullptr, nullptr, nullptr,
        pG2, HC);

    // K6: z = leaky(bn(sum G2*att + on_b) + g) -> d_h
    z_mma<<<dim3(Cc, Nn), blk, ZM_SMEM>>>(
        pG2, patt, pg, on_b, on_g, on_bb, on_m, on_v, ph);

    // K7: out = leaky(bn(ff_w @ z + ff_b) + g)
    conv_mma<MODE_BN_RES_LEAKY, 0><<<dim3(PT, 1, Nn), blk, CV_SMEM>>>(
        ph, pwf + WF_FF, ff_b, nullptr, pg, ff_g, ff_bb, ff_m, ff_v,
        out, Cc);
}

// round 8
// speedup vs baseline: 1.0986x; 1.0782x over previous
#include <cuda_runtime.h>
#include <math.h>
#include <stdint.h>

// Problem constants
#define Nn   32
#define Cc   64
#define Tt   64
#define Vv   204
#define Hh   3
#define QKd  16
#define Pp   13056
#define OQKV 96
#define HC   192

// ---------------- scratch (padded where edge chunks over-read) ----------------
__device__ float d_h   [(size_t)Nn * Cc * Pp + 64];   // gcn conv out; later z
__device__ float d_g   [(size_t)Nn * Cc * Pp + 64];
__device__ float d_qk  [(size_t)Nn * OQKV * Pp + 64];
__device__ float d_wpe [(size_t)OQKV * Pp];
__device__ float d_att [(size_t)Nn * Hh * Tt * Tt];
__device__ float d_attp[(size_t)4 * Nn * Hh * Tt * Tt];
__device__ float d_G2  [(size_t)Nn * HC * Pp + 64];
__device__ float d_wt  [4096 + 6144 + 4096 + 12288];  // tf32: gcn | qkv | ff | w2
__device__ float d_A2  [208 * 208];                   // tf32 zero-padded adjacency [u][v]

#define WT_GCN 0
#define WT_QKV 4096
#define WT_FF  10240
#define WT_W2  14336

enum { MODE_BIAS = 0, MODE_ADD2D = 1, MODE_BN_RES_LEAKY = 2, MODE_NONE = 3 };

// ---------------- helpers ----------------
__device__ __forceinline__ unsigned cvt_tf32(float f) {
    unsigned u;
    asm("cvt.rna.tf32.f32 %0, %1;" : "=r"(u) : "f"(f));
    return u;
}
__device__ __forceinline__ float rna_f(float f) { return __uint_as_float(cvt_tf32(f)); }

__device__ __forceinline__ void mma8(float* d, const unsigned* a, const unsigned* b) {
    asm volatile(
        "mma.sync.aligned.m16n8k8.row.col.f32.tf32.tf32.f32 "
        "{%0,%1,%2,%3},{%4,%5,%6,%7},{%8,%9},{%0,%1,%2,%3};"
        : "+f"(d[0]), "+f"(d[1]), "+f"(d[2]), "+f"(d[3])
        : "r"(a[0]), "r"(a[1]), "r"(a[2]), "r"(a[3]), "r"(b[0]), "r"(b[1]));
}

__device__ __forceinline__ uint32_t smem_u32(const void* p) {
    return (uint32_t)__cvta_generic_to_shared(p);
}
__device__ __forceinline__ void cpa16(uint32_t dst, const void* src) {
    asm volatile("cp.async.cg.shared.global [%0],[%1],16;" :: "r"(dst), "l"(src));
}
__device__ __forceinline__ void cpa16z(uint32_t dst, const void* src, int sz) {
    asm volatile("cp.async.cg.shared.global [%0],[%1],16,%2;" :: "r"(dst), "l"(src), "r"(sz));
}
#define CP_COMMIT() asm volatile("cp.async.commit_group;")
#define CP_WAIT2()  asm volatile("cp.async.wait_group 2;")

// ============================================================================
// prep: tf32-convert all small operands once per call
// ============================================================================
__global__ void prep_kernel(const float* __restrict__ gcn_w, const float* __restrict__ qkv_w,
                            const float* __restrict__ ff_w, const float* __restrict__ on_w,
                            const float* __restrict__ A,
                            float* __restrict__ wt, float* __restrict__ A2)
{
    int i = blockIdx.x * 256 + threadIdx.x;
    if (i < 4096) { wt[WT_GCN + i] = rna_f(gcn_w[i]); return; }
    i -= 4096;
    if (i < 6144) { wt[WT_QKV + i] = rna_f(qkv_w[i]); return; }
    i -= 6144;
    if (i < 4096) { wt[WT_FF + i] = rna_f(ff_w[i]); return; }
    i -= 4096;
    if (i < 12288) {
        int o = i >> 6, cc = i & 63;
        int s = o >> 6, c = o & 63;
        wt[WT_W2 + i] = rna_f(on_w[(size_t)c * HC + s * 64 + cc]);
        return;
    }
    i -= 12288;
    if (i < 208 * 208) {
        int u = i / 208, v = i % 208;
        A2[i] = (u < 204 && v < 204) ? rna_f(A[(size_t)u * 204 + v]) : 0.f;
    }
}

// ============================================================================
// conv_mma (R5): out[n,o,p] = sum_c W[o,c]*in[n,c,p]
// CTA tile: M=64 (Oc), N=256 (P), k-chunk 16, 4-stage ring, 1 sync/chunk.
// 256 thr, 8 warps = 2(M,32)x4(N,64).
// ============================================================================
#define CV_ASZ (64 * 20)
#define CV_BSZ (16 * 264)
#define CV_SMEM (4 * (CV_ASZ + CV_BSZ) * 4)

template <int MODE, int ROUND>
__global__ __launch_bounds__(256, 2)
void conv_mma(const float* __restrict__ in, const float* __restrict__ Wt,
              const float* __restrict__ bias, const float* __restrict__ add2d,
              const float* __restrict__ res,
              const float* __restrict__ bng, const float* __restrict__ bnb,
              const float* __restrict__ bnm, const float* __restrict__ bnv,
              float* __restrict__ out, int Kc, int Oc)
{
    extern __shared__ float sm[];
    float* As = sm;                 // 4 stages [64][20]
    float* Bs = sm + 4 * CV_ASZ;    // 4 stages [16][264]

    const int n  = blockIdx.z;
    const int pt = blockIdx.x * 256;
    const int ot = blockIdx.y * 64;
    const int tid = threadIdx.x, lane = tid & 31, warp = tid >> 5;
    const int wm = warp & 1, wn = warp >> 1;
    const int m0 = wm * 32, n0 = wn * 64;
    const int lr = lane >> 2, kc = lane & 3;

    const float* inN = in + (size_t)n * Kc * Pp + pt;
    const int NCH = Kc >> 4;

    float acc[2][8][4];
    #pragma unroll
    for (int f = 0; f < 2; f++)
        #pragma unroll
        for (int j = 0; j < 8; j++)
            #pragma unroll
            for (int q = 0; q < 4; q++) acc[f][j][q] = 0.f;

    auto prefetch = [&](int c, int stage) {
        float* BsS = Bs + stage * CV_BSZ;
        const float* bsrc = inN + (size_t)(c * 16) * Pp;
        #pragma unroll
        for (int i = 0; i < 4; i++) {
            int e = tid + 256 * i;
            int k = e >> 6, grp = e & 63;
            cpa16(smem_u32(&BsS[k * 264 + grp * 4]), bsrc + (size_t)k * Pp + grp * 4);
        }
        float* AsS = As + stage * CV_ASZ;
        int arow = tid >> 2, agrp = tid & 3;
        int o = ot + arow;
        int ok = (o < Oc);
        cpa16z(smem_u32(&AsS[arow * 20 + agrp * 4]),
               ok ? (Wt + (size_t)o * Kc + c * 16 + agrp * 4) : Wt, ok ? 16 : 0);
    };

    prefetch(0, 0); CP_COMMIT();
    if (NCH > 1) prefetch(1, 1);
    CP_COMMIT();

    for (int c = 0; c < NCH; c++) {
        if (c + 2 < NCH) prefetch(c + 2, (c + 2) & 3);
        CP_COMMIT();
        CP_WAIT2();
        __syncthreads();

        const float* AsS = As + (c & 3) * CV_ASZ;
        const float* BsS = Bs + (c & 3) * CV_BSZ;
        #pragma unroll
        for (int g = 0; g < 2; g++) {
            unsigned a[2][4];
            #pragma unroll
            for (int f = 0; f < 2; f++) {
                a[f][0] = __float_as_uint(AsS[(m0 + f * 16 + lr    ) * 20 + g * 8 + kc    ]);
                a[f][1] = __float_as_uint(AsS[(m0 + f * 16 + lr + 8) * 20 + g * 8 + kc    ]);
                a[f][2] = __float_as_uint(AsS[(m0 + f * 16 + lr    ) * 20 + g * 8 + kc + 4]);
                a[f][3] = __float_as_uint(AsS[(m0 + f * 16 + lr + 8) * 20 + g * 8 + kc + 4]);
            }
            #pragma unroll
            for (int j = 0; j < 8; j++) {
                unsigned b[2];
                b[0] = __float_as_uint(BsS[(g * 8 + kc    ) * 264 + n0 + 8 * j + lr]);
                b[1] = __float_as_uint(BsS[(g * 8 + kc + 4) * 264 + n0 + 8 * j + lr]);
                mma8(acc[0][j], a[0], b);
                mma8(acc[1][j], a[1], b);
            }
        }
    }

    #pragma unroll
    for (int f = 0; f < 2; f++) {
        #pragma unroll
        for (int half = 0; half < 2; half++) {
            int o = ot + m0 + f * 16 + lr + half * 8;
            if (o >= Oc) continue;
            size_t obase = ((size_t)n * Oc + o) * Pp;
            if (MODE == MODE_NONE) {
                #pragma unroll
                for (int j = 0; j < 8; j++) {
                    int p = pt + n0 + 8 * j + 2 * kc;
                    float va = acc[f][j][half * 2], vb = acc[f][j][half * 2 + 1];
                    if (ROUND) { va = rna_f(va); vb = rna_f(vb); }
                    *(float2*)(out + obase + p) = make_float2(va, vb);
                }
            } else if (MODE == MODE_BIAS) {
                float b = bias[o];
                #pragma unroll
                for (int j = 0; j < 8; j++) {
                    int p = pt + n0 + 8 * j + 2 * kc;
                    float va = acc[f][j][half * 2] + b, vb = acc[f][j][half * 2 + 1] + b;
                    if (ROUND) { va = rna_f(va); vb = rna_f(vb); }
                    *(float2*)(out + obase + p) = make_float2(va, vb);
                }
            } else if (MODE == MODE_ADD2D) {
                size_t abase = (size_t)o * Pp;
                #pragma unroll
                for (int j = 0; j < 8; j++) {
                    int p = pt + n0 + 8 * j + 2 * kc;
                    float2 av = *(const float2*)(add2d + abase + p);
                    float va = acc[f][j][half * 2] + av.x, vb = acc[f][j][half * 2 + 1] + av.y;
                    if (ROUND) { va = rna_f(va); vb = rna_f(vb); }
                    *(float2*)(out + obase + p) = make_float2(va, vb);
                }
            } else { // MODE_BN_RES_LEAKY
                float s  = bng[o] * rsqrtf(bnv[o] + 1e-5f);
                float sh = bnb[o] - bnm[o] * s + bias[o] * s;
                #pragma unroll
                for (int j = 0; j < 8; j++) {
                    int p = pt + n0 + 8 * j + 2 * kc;
                    float2 rv = *(const float2*)(res + obase + p);
                    float va = acc[f][j][half * 2]     * s + sh + rv.x;
                    float vb = acc[f][j][half * 2 + 1] * s + sh + rv.y;
                    va = (va > 0.f) ? va : 0.1f * va;
                    vb = (vb > 0.f) ? vb : 0.1f * vb;
                    if (ROUND) { va = rna_f(va); vb = rna_f(vb); }
                    *(float2*)(out + obase + p) = make_float2(va, vb);
                }
            }
        }
    }
}

// ============================================================================
// adj_mma (R5): g[r,u] = relu(bn_c(sum_v h[r,v]*A2[u,v]) + x[r,u])
// M=64(r), N=208(u), K=208 padded (13 chunks), 4-stage ring, 256 thr.
// ============================================================================
#define AD_ASZ (64 * 20)
#define AD_BSZ (208 * 20)
#define AD_SMEM (4 * (AD_ASZ + AD_BSZ) * 4)

__global__ __launch_bounds__(256, 2)
void adj_mma(const float* __restrict__ h, const float* __restrict__ A2,
             const float* __restrict__ x,
             const float* __restrict__ bng, const float* __restrict__ bnb,
             const float* __restrict__ bnm, const float* __restrict__ bnv,
             float* __restrict__ out)
{
    extern __shared__ float sm[];
    float* As = sm;
    float* Bs = sm + 4 * AD_ASZ;

    const int rt = blockIdx.x * 64;
    const int tid = threadIdx.x, lane = tid & 31, warp = tid >> 5;
    const int wm = warp & 3, wn = warp >> 2;
    const int m0 = wm * 16, nb0 = wn * 104;
    const int lr = lane >> 2, kc = lane & 3;

    const int ch  = (rt >> 6) & 63;
    const float s  = bng[ch] * rsqrtf(bnv[ch] + 1e-5f);
    const float sh = bnb[ch] - bnm[ch] * s;

    float acc[13][4];
    #pragma unroll
    for (int j = 0; j < 13; j++)
        #pragma unroll
        for (int q = 0; q < 4; q++) acc[j][q] = 0.f;

    const int arow = tid >> 2, agrp = tid & 3;
    const int NCH = 13;

    auto prefetch = [&](int c, int stage) {
        float* BsS = Bs + stage * AD_BSZ;
        #pragma unroll
        for (int i = 0; i < 4; i++) {
            int e = tid + 256 * i;
            if (e < 832) {
                int u = e >> 2, grp = e & 3;
                cpa16(smem_u32(&BsS[u * 20 + grp * 4]), A2 + (size_t)u * 208 + c * 16 + grp * 4);
            }
        }
        float* AsS = As + stage * AD_ASZ;
        cpa16(smem_u32(&AsS[arow * 20 + agrp * 4]),
              h + (size_t)(rt + arow) * 204 + c * 16 + agrp * 4);
    };

    prefetch(0, 0); CP_COMMIT();
    prefetch(1, 1); CP_COMMIT();

    for (int c = 0; c < NCH; c++) {
        if (c + 2 < NCH) prefetch(c + 2, (c + 2) & 3);
        CP_COMMIT();
        CP_WAIT2();
        __syncthreads();

        const float* AsS = As + (c & 3) * AD_ASZ;
        const float* BsS = Bs + (c & 3) * AD_BSZ;
        #pragma unroll
        for (int g = 0; g < 2; g++) {
            unsigned a[4];
            a[0] = __float_as_uint(AsS[(m0 + lr    ) * 20 + g * 8 + kc    ]);
            a[1] = __float_as_uint(AsS[(m0 + lr + 8) * 20 + g * 8 + kc    ]);
            a[2] = __float_as_uint(AsS[(m0 + lr    ) * 20 + g * 8 + kc + 4]);
            a[3] = __float_as_uint(AsS[(m0 + lr + 8) * 20 + g * 8 + kc + 4]);
            #pragma unroll
            for (int j = 0; j < 13; j++) {
                unsigned b[2];
                b[0] = __float_as_uint(BsS[(nb0 + 8 * j + lr) * 20 + g * 8 + kc    ]);
                b[1] = __float_as_uint(BsS[(nb0 + 8 * j + lr) * 20 + g * 8 + kc + 4]);
                mma8(acc[j], a, b);
            }
        }
    }

    #pragma unroll
    for (int half = 0; half < 2; half++) {
        int r = rt + m0 + lr + half * 8;
        size_t rbase = (size_t)r * 204;
        #pragma unroll
        for (int j = 0; j < 13; j++) {
            int u = nb0 + 8 * j + 2 * kc;
            if (u < 204) {
                float2 xv = *(const float2*)(x + rbase + u);
                float va = acc[j][half * 2]     * s + sh + xv.x;
                float vb = acc[j][half * 2 + 1] * s + sh + xv.y;
                *(float2*)(out + rbase + u) =
                    make_float2(rna_f(fmaxf(va, 0.f)), rna_f(fmaxf(vb, 0.f)));
            }
        }
    }
}

// ============================================================================
// attn_mma (R5): part[z,n,h,t,q] = sum_{c in 4-chunk z, v} q[c,t,v]*k[c,q,v]
// ============================================================================
#define AT_QSZ (64 * 20)
#define AT_SMEM (4 * 2 * AT_QSZ * 4)

__global__ __launch_bounds__(256, 4)
void attn_mma(const float* __restrict__ qk, float* __restrict__ part)
{
    extern __shared__ float sm[];
    float* Qs = sm;
    float* Ks = sm + 4 * AT_QSZ;

    const int hh = blockIdx.x, n = blockIdx.y, z = blockIdx.z;
    const int cc0 = z * 4;
    const int tid = threadIdx.x, lane = tid & 31, warp = tid >> 5;
    const int wm = warp & 3, wn = warp >> 2;
    const int m0 = wm * 16, nb0 = wn * 32;
    const int lr = lane >> 2, kc = lane & 3;

    const float* qbase = qk + ((size_t)n * OQKV + hh * QKd) * Pp;
    const float* kbase = qk + ((size_t)n * OQKV + Hh * QKd + hh * QKd) * Pp;

    const int arow = tid >> 2, agrp = tid & 3;
    const int NCH = 52;

    float acc[4][4];
    #pragma unroll
    for (int j = 0; j < 4; j++)
        #pragma unroll
        for (int q = 0; q < 4; q++) acc[j][q] = 0.f;

    auto prefetch = [&](int c, int stage) {
        int ci = cc0 + (c / 13);
        int vb = (c % 13) * 16;
        int v = vb + agrp * 4;
        int ok = (v < 204);
        const float* qs = qbase + (size_t)ci * Pp + (size_t)arow * 204 + v;
        const float* ks = kbase + (size_t)ci * Pp + (size_t)arow * 204 + v;
        cpa16z(smem_u32(&Qs[stage * AT_QSZ + arow * 20 + agrp * 4]), ok ? qs : qk, ok ? 16 : 0);
        cpa16z(smem_u32(&Ks[stage * AT_QSZ + arow * 20 + agrp * 4]), ok ? ks : qk, ok ? 16 : 0);
    };

    prefetch(0, 0); CP_COMMIT();
    prefetch(1, 1); CP_COMMIT();

    for (int c = 0; c < NCH; c++) {
        if (c + 2 < NCH) prefetch(c + 2, (c + 2) & 3);
        CP_COMMIT();
        CP_WAIT2();
        __syncthreads();

        const float* QsS = Qs + (c & 3) * AT_QSZ;
        const float* KsS = Ks + (c & 3) * AT_QSZ;
        #pragma unroll
        for (int g = 0; g < 2; g++) {
            unsigned a[4];
            a[0] = __float_as_uint(QsS[(m0 + lr    ) * 20 + g * 8 + kc    ]);
            a[1] = __float_as_uint(QsS[(m0 + lr + 8) * 20 + g * 8 + kc    ]);
            a[2] = __float_as_uint(QsS[(m0 + lr    ) * 20 + g * 8 + kc + 4]);
            a[3] = __float_as_uint(QsS[(m0 + lr + 8) * 20 + g * 8 + kc + 4]);
            #pragma unroll
            for (int j = 0; j < 4; j++) {
                unsigned b[2];
                b[0] = __float_as_uint(KsS[(nb0 + 8 * j + lr) * 20 + g * 8 + kc    ]);
                b[1] = __float_as_uint(KsS[(nb0 + 8 * j + lr) * 20 + g * 8 + kc + 4]);
                mma8(acc[j], a, b);
            }
        }
    }

    float* pb = part + (((size_t)z * Nn + n) * Hh + hh) * 4096;
    #pragma unroll
    for (int half = 0; half < 2; half++) {
        int t = m0 + lr + half * 8;
        #pragma unroll
        for (int j = 0; j < 4; j++) {
            int q = nb0 + 8 * j + 2 * kc;
            *(float2*)(pb + (size_t)t * 64 + q) =
                make_float2(acc[j][half * 2], acc[j][half * 2 + 1]);
        }
    }
}

__global__ void attn_combine_kernel(const float* __restrict__ part,
                                    const float* __restrict__ alphas,
                                    const float* __restrict__ att1s,
                                    float* __restrict__ att)
{
    int idx = blockIdx.x * blockDim.x + threadIdx.x;
    const int total = Nn * Hh * Tt * Tt;
    if (idx >= total) return;
    int tq = idx & (Tt * Tt - 1);
    int h  = (idx / (Tt * Tt)) % Hh;
    float p = part[idx] + part[(size_t)total + idx]
            + part[2 * (size_t)total + idx] + part[3 * (size_t)total + idx];
    const float inv = 1.0f / (float)(QKd * Vv);
    att[idx] = rna_f(tanhf(p * inv) * alphas[h] + att1s[(size_t)h * Tt * Tt + tq]);
}

// ============================================================================
// z_mma (R5): z[n,c,q,v] = leaky(bn_c(sum_{s,t} G2[n,s,c,t,v]*att[n,s,t,q]) + g)
// ============================================================================
#define ZM_ASZ (16 * 72)
#define ZM_BSZ (16 * 232)
#define ZM_SMEM (4 * (ZM_ASZ + ZM_BSZ) * 4)

__global__ __launch_bounds__(256, 2)
void z_mma(const float* __restrict__ G2, const float* __restrict__ att,
           const float* __restrict__ g,
           const float* __restrict__ on_b, const float* __restrict__ on_g,
           const float* __restrict__ on_bb, const float* __restrict__ on_m,
           const float* __restrict__ on_v,
           float* __restrict__ out)
{
    extern __shared__ float sm[];
    float* As = sm;                 // 4 stages [t=16][q=64 pad 72]
    float* Bs = sm + 4 * ZM_ASZ;    // 4 stages [t=16][v pad 232]

    const int cch = blockIdx.x, n = blockIdx.y;
    const int tid = threadIdx.x, lane = tid & 31, warp = tid >> 5;
    const int wm = warp & 3, wn = warp >> 2;
    const int m0 = wm * 16, nb0 = wn * 104;
    const int lr = lane >> 2, kc = lane & 3;

    float acc[13][4];
    #pragma unroll
    for (int j = 0; j < 13; j++)
        #pragma unroll
        for (int q = 0; q < 4; q++) acc[j][q] = 0.f;

    const int NCH = 12;

    auto prefetch = [&](int c, int stage) {
        int s  = c >> 2;
        int tb = (c & 3) * 16;
        const float* gb = G2 + ((size_t)n * HC + s * 64 + cch) * Pp;
        float* BsS = Bs + stage * ZM_BSZ;
        #pragma unroll
        for (int i = 0; i < 4; i++) {
            int e = tid + 256 * i;
            if (e < 832) {
                int trow = e / 52, grp = e % 52;
                int ok = (grp < 51);
                cpa16z(smem_u32(&BsS[trow * 232 + grp * 4]),
                       ok ? (gb + (size_t)(tb + trow) * 204 + grp * 4) : gb, ok ? 16 : 0);
            }
        }
        float* AsS = As + stage * ZM_ASZ;
        int trow = tid >> 4, grp = tid & 15;
        cpa16(smem_u32(&AsS[trow * 72 + grp * 4]),
              att + ((size_t)(n * Hh + s)) * 4096 + (size_t)(tb + trow) * 64 + grp * 4);
    };

    prefetch(0, 0); CP_COMMIT();
    prefetch(1, 1); CP_COMMIT();

    for (int c = 0; c < NCH; c++) {
        if (c + 2 < NCH) prefetch(c + 2, (c + 2) & 3);
        CP_COMMIT();
        CP_WAIT2();
        __syncthreads();

        const float* AsS = As + (c & 3) * ZM_ASZ;
        const float* BsS = Bs + (c & 3) * ZM_BSZ;
        #pragma unroll
        for (int g8 = 0; g8 < 2; g8++) {
            unsigned a[4];
            a[0] = __float_as_uint(AsS[(g8 * 8 + kc    ) * 72 + m0 + lr    ]);
            a[1] = __float_as_uint(AsS[(g8 * 8 + kc    ) * 72 + m0 + lr + 8]);
            a[2] = __float_as_uint(AsS[(g8 * 8 + kc + 4) * 72 + m0 + lr    ]);
            a[3] = __float_as_uint(AsS[(g8 * 8 + kc + 4) * 72 + m0 + lr + 8]);
            #pragma unroll
            for (int j = 0; j < 13; j++) {
                unsigned b[2];
                b[0] = __float_as_uint(BsS[(g8 * 8 + kc    ) * 232 + nb0 + 8 * j + lr]);
                b[1] = __float_as_uint(BsS[(g8 * 8 + kc + 4) * 232 + nb0 + 8 * j + lr]);
                mma8(acc[j], a, b);
            }
        }
    }

    const float sbn = on_g[cch] * rsqrtf(on_v[cch] + 1e-5f);
    const float sh  = on_bb[cch] - on_m[cch] * sbn + on_b[cch] * sbn;
    const float* gres = g + ((size_t)n * Cc + cch) * Pp;
    float* zb = out + ((size_t)n * Cc + cch) * Pp;

    #pragma unroll
    for (int half = 0; half < 2; half++) {
        int q = m0 + lr + half * 8;
        #pragma unroll
        for (int j = 0; j < 13; j++) {
            int v = nb0 + 8 * j + 2 * kc;
            if (v < 204) {
                float2 rv = *(const float2*)(gres + (size_t)q * 204 + v);
                float va = acc[j][half * 2]     * sbn + sh + rv.x;
                float vb = acc[j][half * 2 + 1] * sbn + sh + rv.y;
                va = (va > 0.f) ? va : 0.1f * va;
                vb = (vb > 0.f) ? vb : 0.1f * vb;
                *(float2*)(zb + (size_t)q * 204 + v) = make_float2(rna_f(va), rna_f(vb));
            }
        }
    }
}

// ---------------- launch (stream-parallel fork/join) ----------------
extern "C" void kernel_launch(void* const* d_in, const int* in_sizes, int n_in,
                              void* d_out, int out_size)
{
    const float* x      = (const float*)d_in[0];
    const float* A      = (const float*)d_in[1];
    const float* gcn_w  = (const float*)d_in[2];
    const float* gcn_b  = (const float*)d_in[3];
    const float* gcn_g  = (const float*)d_in[4];
    const float* gcn_bb = (const float*)d_in[5];
    const float* gcn_m  = (const float*)d_in[6];
    const float* gcn_v  = (const float*)d_in[7];
    const float* pe     = (const float*)d_in[8];
    const float* qkv_w  = (const float*)d_in[9];
    const float* qkv_b  = (const float*)d_in[10];
    const float* alphas = (const float*)d_in[11];
    const float* att1s  = (const float*)d_in[12];
    const float* on_w   = (const float*)d_in[13];
    const float* on_b   = (const float*)d_in[14];
    const float* on_g   = (const float*)d_in[15];
    const float* on_bb  = (const float*)d_in[16];
    const float* on_m   = (const float*)d_in[17];
    const float* on_v   = (const float*)d_in[18];
    const float* ff_w   = (const float*)d_in[19];
    const float* ff_b   = (const float*)d_in[20];
    const float* ff_g   = (const float*)d_in[21];
    const float* ff_bb  = (const float*)d_in[22];
    const float* ff_m   = (const float*)d_in[23];
    const float* ff_v   = (const float*)d_in[24];
    float* out = (float*)d_out;

    float *ph, *pg, *pqk, *pwpe, *patt, *pattp, *pG2, *pwt, *pA2;
    cudaGetSymbolAddress((void**)&ph,    d_h);
    cudaGetSymbolAddress((void**)&pg,    d_g);
    cudaGetSymbolAddress((void**)&pqk,   d_qk);
    cudaGetSymbolAddress((void**)&pwpe,  d_wpe);
    cudaGetSymbolAddress((void**)&patt,  d_att);
    cudaGetSymbolAddress((void**)&pattp, d_attp);
    cudaGetSymbolAddress((void**)&pG2,   d_G2);
    cudaGetSymbolAddress((void**)&pwt,   d_wt);
    cudaGetSymbolAddress((void**)&pA2,   d_A2);

    static int init_done = 0;
    static cudaStream_t s2;
    static cudaEvent_t evP, evW, evG, evJ;
    if (!init_done) {
        cudaFuncSetAttribute(conv_mma<MODE_BIAS, 0>, cudaFuncAttributeMaxDynamicSharedMemorySize, CV_SMEM);
        cudaFuncSetAttribute(conv_mma<MODE_BIAS, 1>, cudaFuncAttributeMaxDynamicSharedMemorySize, CV_SMEM);
        cudaFuncSetAttribute(conv_mma<MODE_ADD2D, 1>, cudaFuncAttributeMaxDynamicSharedMemorySize, CV_SMEM);
        cudaFuncSetAttribute(conv_mma<MODE_NONE, 1>, cudaFuncAttributeMaxDynamicSharedMemorySize, CV_SMEM);
        cudaFuncSetAttribute(conv_mma<MODE_BN_RES_LEAKY, 0>, cudaFuncAttributeMaxDynamicSharedMemorySize, CV_SMEM);
        cudaFuncSetAttribute(adj_mma, cudaFuncAttributeMaxDynamicSharedMemorySize, AD_SMEM);
        cudaFuncSetAttribute(attn_mma, cudaFuncAttributeMaxDynamicSharedMemorySize, AT_SMEM);
        cudaFuncSetAttribute(z_mma, cudaFuncAttributeMaxDynamicSharedMemorySize, ZM_SMEM);
        cudaStreamCreateWithFlags(&s2, cudaStreamNonBlocking);
        cudaEventCreateWithFlags(&evP, cudaEventDisableTiming);
        cudaEventCreateWithFlags(&evW, cudaEventDisableTiming);
        cudaEventCreateWithFlags(&evG, cudaEventDisableTiming);
        cudaEventCreateWithFlags(&evJ, cudaEventDisableTiming);
        init_done = 1;
    }

    dim3 blk(256);

    // [0] P0: tf32 pre-convert small operands
    prep_kernel<<<(4096 + 6144 + 4096 + 12288 + 208 * 208 + 255) / 256, blk>>>(
        gcn_w, qkv_w, ff_w, on_w, A, pwt, pA2);
    cudaEventRecord(evP, 0);

    // [s2] K0: wpe = qkv_w @ pe + qkv_b   (runs beside K1/K2)
    cudaStreamWaitEvent(s2, evP, 0);
    conv_mma<MODE_BIAS, 0><<<dim3(Pp / 256, 2, 1), blk, CV_SMEM, s2>>>(
        pe, pwt + WT_QKV, qkv_b, nullptr, nullptr, nullptr, nullptr, nullptr, nullptr,
        pwpe, Cc, OQKV);
    cudaEventRecord(evW, s2);

    // [0] K1: h = gcn conv
    conv_mma<MODE_BIAS, 1><<<dim3(Pp / 256, 1, Nn), blk, CV_SMEM>>>(
        x, pwt + WT_GCN, gcn_b, nullptr, nullptr, nullptr, nullptr, nullptr, nullptr,
        ph, Cc, Cc);

    // [0] K2: g = relu(bn(A @ h) + x)
    adj_mma<<<dim3((Nn * Cc * Tt) / 64, 1, 1), blk, AD_SMEM>>>(
        ph, pA2, x, gcn_g, gcn_bb, gcn_m, gcn_v, pg);
    cudaEventRecord(evG, 0);

    // [s2] K5: G2 = W2 @ g   (runs fully beside K3 + K4)
    cudaStreamWaitEvent(s2, evG, 0);
    conv_mma<MODE_NONE, 1><<<dim3(Pp / 256, 3, Nn), blk, CV_SMEM, s2>>>(
        pg, pwt + WT_W2, nullptr, nullptr, nullptr, nullptr, nullptr, nullptr, nullptr,
        pG2, Cc, HC);
    cudaEventRecord(evJ, s2);

    // [0] K3: qk = qkv_w @ g + wpe   (needs wpe from s2)
    cudaStreamWaitEvent(0, evW, 0);
    conv_mma<MODE_ADD2D, 1><<<dim3(Pp / 256, 2, Nn), blk, CV_SMEM>>>(
        pg, pwt + WT_QKV, nullptr, pwpe, nullptr, nullptr, nullptr, nullptr, nullptr,
        pqk, Cc, OQKV);

    // [0] K4: attention scores + combine
    attn_mma<<<dim3(Hh, Nn, 4), blk, AT_SMEM>>>(pqk, pattp);
    attn_combine_kernel<<<(Nn * Hh * Tt * Tt + 255) / 256, blk>>>(pattp, alphas, att1s, patt);

    // [0] join: K6 needs G2 from s2
    cudaStreamWaitEvent(0, evJ, 0);

    // [0] K6: z = leaky(bn(sum G2*att + on_b) + g) -> d_h
    z_mma<<<dim3(Cc, Nn), blk, ZM_SMEM>>>(
        pG2, patt, pg, on_b, on_g, on_bb, on_m, on_v, ph);

    // [0] K7: out = leaky(bn(ff_w @ z + ff_b) + g)
    conv_mma<MODE_BN_RES_LEAKY, 0><<<dim3(Pp / 256, 1, Nn), blk, CV_SMEM>>>(
        ph, pwt + WT_FF, ff_b, nullptr, pg, ff_g, ff_bb, ff_m, ff_v,
        out, Cc, Cc);
}

// round 10
// speedup vs baseline: 1.1149x; 1.0149x over previous
#include <cuda_runtime.h>
#include <math.h>
#include <stdint.h>

// Problem constants
#define Nn   32
#define Cc   64
#define Tt   64
#define Vv   204
#define Hh   3
#define QKd  16
#define Pp   13056
#define OQKV 96
#define HC   192

#define NB   16   // batches per segment (2 segments)

// ---------------- scratch ----------------
__device__ float d_h   [(size_t)Nn * Cc * Pp + 64];
__device__ float d_g   [(size_t)Nn * Cc * Pp + 64];
__device__ float d_qk  [(size_t)Nn * OQKV * Pp + 64];
__device__ float d_wpe [(size_t)OQKV * Pp];
__device__ float d_att [(size_t)Nn * Hh * Tt * Tt];
__device__ float d_attp[(size_t)4 * Nn * Hh * Tt * Tt];
__device__ float d_G2  [(size_t)Nn * HC * Pp + 64];
__device__ float d_wt  [4096 + 6144 + 4096 + 12288];  // tf32: gcn | qkv | ff | w2
__device__ float d_A2  [208 * 208];

#define WT_GCN 0
#define WT_QKV 4096
#define WT_FF  10240
#define WT_W2  14336

enum { MODE_BIAS = 0, MODE_ADD2D = 1, MODE_BN_RES_LEAKY = 2, MODE_NONE = 3 };

// ---------------- helpers ----------------
__device__ __forceinline__ unsigned cvt_tf32(float f) {
    unsigned u;
    asm("cvt.rna.tf32.f32 %0, %1;" : "=r"(u) : "f"(f));
    return u;
}
__device__ __forceinline__ float rna_f(float f) { return __uint_as_float(cvt_tf32(f)); }

__device__ __forceinline__ void mma8(float* d, const unsigned* a, const unsigned* b) {
    asm volatile(
        "mma.sync.aligned.m16n8k8.row.col.f32.tf32.tf32.f32 "
        "{%0,%1,%2,%3},{%4,%5,%6,%7},{%8,%9},{%0,%1,%2,%3};"
        : "+f"(d[0]), "+f"(d[1]), "+f"(d[2]), "+f"(d[3])
        : "r"(a[0]), "r"(a[1]), "r"(a[2]), "r"(a[3]), "r"(b[0]), "r"(b[1]));
}

__device__ __forceinline__ uint32_t smem_u32(const void* p) {
    return (uint32_t)__cvta_generic_to_shared(p);
}
__device__ __forceinline__ void cpa16(uint32_t dst, const void* src) {
    asm volatile("cp.async.cg.shared.global [%0],[%1],16;" :: "r"(dst), "l"(src));
}
__device__ __forceinline__ void cpa16z(uint32_t dst, const void* src, int sz) {
    asm volatile("cp.async.cg.shared.global [%0],[%1],16,%2;" :: "r"(dst), "l"(src), "r"(sz));
}
#define CP_COMMIT() asm volatile("cp.async.commit_group;")
#define CP_WAIT2()  asm volatile("cp.async.wait_group 2;")

// ============================================================================
// prep
// ============================================================================
__global__ void prep_kernel(const float* __restrict__ gcn_w, const float* __restrict__ qkv_w,
                            const float* __restrict__ ff_w, const float* __restrict__ on_w,
                            const float* __restrict__ A,
                            float* __restrict__ wt, float* __restrict__ A2)
{
    int i = blockIdx.x * 256 + threadIdx.x;
    if (i < 4096) { wt[WT_GCN + i] = rna_f(gcn_w[i]); return; }
    i -= 4096;
    if (i < 6144) { wt[WT_QKV + i] = rna_f(qkv_w[i]); return; }
    i -= 6144;
    if (i < 4096) { wt[WT_FF + i] = rna_f(ff_w[i]); return; }
    i -= 4096;
    if (i < 12288) {
        int o = i >> 6, cc = i & 63;
        int s = o >> 6, c = o & 63;
        wt[WT_W2 + i] = rna_f(on_w[(size_t)c * HC + s * 64 + cc]);
        return;
    }
    i -= 12288;
    if (i < 208 * 208) {
        int u = i / 208, v = i % 208;
        A2[i] = (u < 204 && v < 204) ? rna_f(A[(size_t)u * 204 + v]) : 0.f;
    }
}

// ============================================================================
// conv_mma (R5 + batch offset)
// ============================================================================
#define CV_ASZ (64 * 20)
#define CV_BSZ (16 * 264)
#define CV_SMEM (4 * (CV_ASZ + CV_BSZ) * 4)

template <int MODE, int ROUND>
__global__ __launch_bounds__(256, 2)
void conv_mma(const float* __restrict__ in, const float* __restrict__ Wt,
              const float* __restrict__ bias, const float* __restrict__ add2d,
              const float* __restrict__ res,
              const float* __restrict__ bng, const float* __restrict__ bnb,
              const float* __restrict__ bnm, const float* __restrict__ bnv,
              float* __restrict__ out, int Kc, int Oc, int nbase)
{
    extern __shared__ float sm[];
    float* As = sm;
    float* Bs = sm + 4 * CV_ASZ;

    const int n  = blockIdx.z + nbase;
    const int pt = blockIdx.x * 256;
    const int ot = blockIdx.y * 64;
    const int tid = threadIdx.x, lane = tid & 31, warp = tid >> 5;
    const int wm = warp & 1, wn = warp >> 1;
    const int m0 = wm * 32, n0 = wn * 64;
    const int lr = lane >> 2, kc = lane & 3;

    const float* inN = in + (size_t)n * Kc * Pp + pt;
    const int NCH = Kc >> 4;

    float acc[2][8][4];
    #pragma unroll
    for (int f = 0; f < 2; f++)
        #pragma unroll
        for (int j = 0; j < 8; j++)
            #pragma unroll
            for (int q = 0; q < 4; q++) acc[f][j][q] = 0.f;

    auto prefetch = [&](int c, int stage) {
        float* BsS = Bs + stage * CV_BSZ;
        const float* bsrc = inN + (size_t)(c * 16) * Pp;
        #pragma unroll
        for (int i = 0; i < 4; i++) {
            int e = tid + 256 * i;
            int k = e >> 6, grp = e & 63;
            cpa16(smem_u32(&BsS[k * 264 + grp * 4]), bsrc + (size_t)k * Pp + grp * 4);
        }
        float* AsS = As + stage * CV_ASZ;
        int arow = tid >> 2, agrp = tid & 3;
        int o = ot + arow;
        int ok = (o < Oc);
        cpa16z(smem_u32(&AsS[arow * 20 + agrp * 4]),
               ok ? (Wt + (size_t)o * Kc + c * 16 + agrp * 4) : Wt, ok ? 16 : 0);
    };

    prefetch(0, 0); CP_COMMIT();
    if (NCH > 1) prefetch(1, 1);
    CP_COMMIT();

    for (int c = 0; c < NCH; c++) {
        if (c + 2 < NCH) prefetch(c + 2, (c + 2) & 3);
        CP_COMMIT();
        CP_WAIT2();
        __syncthreads();

        const float* AsS = As + (c & 3) * CV_ASZ;
        const float* BsS = Bs + (c & 3) * CV_BSZ;
        #pragma unroll
        for (int g = 0; g < 2; g++) {
            unsigned a[2][4];
            #pragma unroll
            for (int f = 0; f < 2; f++) {
                a[f][0] = __float_as_uint(AsS[(m0 + f * 16 + lr    ) * 20 + g * 8 + kc    ]);
                a[f][1] = __float_as_uint(AsS[(m0 + f * 16 + lr + 8) * 20 + g * 8 + kc    ]);
                a[f][2] = __float_as_uint(AsS[(m0 + f * 16 + lr    ) * 20 + g * 8 + kc + 4]);
                a[f][3] = __float_as_uint(AsS[(m0 + f * 16 + lr + 8) * 20 + g * 8 + kc + 4]);
            }
            #pragma unroll
            for (int j = 0; j < 8; j++) {
                unsigned b[2];
                b[0] = __float_as_uint(BsS[(g * 8 + kc    ) * 264 + n0 + 8 * j + lr]);
                b[1] = __float_as_uint(BsS[(g * 8 + kc + 4) * 264 + n0 + 8 * j + lr]);
                mma8(acc[0][j], a[0], b);
                mma8(acc[1][j], a[1], b);
            }
        }
    }

    #pragma unroll
    for (int f = 0; f < 2; f++) {
        #pragma unroll
        for (int half = 0; half < 2; half++) {
            int o = ot + m0 + f * 16 + lr + half * 8;
            if (o >= Oc) continue;
            size_t obase = ((size_t)n * Oc + o) * Pp;
            if (MODE == MODE_NONE) {
                #pragma unroll
                for (int j = 0; j < 8; j++) {
                    int p = pt + n0 + 8 * j + 2 * kc;
                    float va = acc[f][j][half * 2], vb = acc[f][j][half * 2 + 1];
                    if (ROUND) { va = rna_f(va); vb = rna_f(vb); }
                    *(float2*)(out + obase + p) = make_float2(va, vb);
                }
            } else if (MODE == MODE_BIAS) {
                float b = bias[o];
                #pragma unroll
                for (int j = 0; j < 8; j++) {
                    int p = pt + n0 + 8 * j + 2 * kc;
                    float va = acc[f][j][half * 2] + b, vb = acc[f][j][half * 2 + 1] + b;
                    if (ROUND) { va = rna_f(va); vb = rna_f(vb); }
                    *(float2*)(out + obase + p) = make_float2(va, vb);
                }
            } else if (MODE == MODE_ADD2D) {
                size_t abase = (size_t)o * Pp;
                #pragma unroll
                for (int j = 0; j < 8; j++) {
                    int p = pt + n0 + 8 * j + 2 * kc;
                    float2 av = *(const float2*)(add2d + abase + p);
                    float va = acc[f][j][half * 2] + av.x, vb = acc[f][j][half * 2 + 1] + av.y;
                    if (ROUND) { va = rna_f(va); vb = rna_f(vb); }
                    *(float2*)(out + obase + p) = make_float2(va, vb);
                }
            } else {
                float s  = bng[o] * rsqrtf(bnv[o] + 1e-5f);
                float sh = bnb[o] - bnm[o] * s + bias[o] * s;
                #pragma unroll
                for (int j = 0; j < 8; j++) {
                    int p = pt + n0 + 8 * j + 2 * kc;
                    float2 rv = *(const float2*)(res + obase + p);
                    float va = acc[f][j][half * 2]     * s + sh + rv.x;
                    float vb = acc[f][j][half * 2 + 1] * s + sh + rv.y;
                    va = (va > 0.f) ? va : 0.1f * va;
                    vb = (vb > 0.f) ? vb : 0.1f * vb;
                    if (ROUND) { va = rna_f(va); vb = rna_f(vb); }
                    *(float2*)(out + obase + p) = make_float2(va, vb);
                }
            }
        }
    }
}

// ============================================================================
// adj_mma (R5 + row offset)
// ============================================================================
#define AD_ASZ (64 * 20)
#define AD_BSZ (208 * 20)
#define AD_SMEM (4 * (AD_ASZ + AD_BSZ) * 4)

__global__ __launch_bounds__(256, 2)
void adj_mma(const float* __restrict__ h, const float* __restrict__ A2,
             const float* __restrict__ x,
             const float* __restrict__ bng, const float* __restrict__ bnb,
             const float* __restrict__ bnm, const float* __restrict__ bnv,
             float* __restrict__ out, int rbase)
{
    extern __shared__ float sm[];
    float* As = sm;
    float* Bs = sm + 4 * AD_ASZ;

    const int rt = blockIdx.x * 64 + rbase;
    const int tid = threadIdx.x, lane = tid & 31, warp = tid >> 5;
    const int wm = warp & 3, wn = warp >> 2;
    const int m0 = wm * 16, nb0 = wn * 104;
    const int lr = lane >> 2, kc = lane & 3;

    const int ch  = (rt >> 6) & 63;
    const float s  = bng[ch] * rsqrtf(bnv[ch] + 1e-5f);
    const float sh = bnb[ch] - bnm[ch] * s;

    float acc[13][4];
    #pragma unroll
    for (int j = 0; j < 13; j++)
        #pragma unroll
        for (int q = 0; q < 4; q++) acc[j][q] = 0.f;

    const int arow = tid >> 2, agrp = tid & 3;
    const int NCH = 13;

    auto prefetch = [&](int c, int stage) {
        float* BsS = Bs + stage * AD_BSZ;
        #pragma unroll
        for (int i = 0; i < 4; i++) {
            int e = tid + 256 * i;
            if (e < 832) {
                int u = e >> 2, grp = e & 3;
                cpa16(smem_u32(&BsS[u * 20 + grp * 4]), A2 + (size_t)u * 208 + c * 16 + grp * 4);
            }
        }
        float* AsS = As + stage * AD_ASZ;
        cpa16(smem_u32(&AsS[arow * 20 + agrp * 4]),
              h + (size_t)(rt + arow) * 204 + c * 16 + agrp * 4);
    };

    prefetch(0, 0); CP_COMMIT();
    prefetch(1, 1); CP_COMMIT();

    for (int c = 0; c < NCH; c++) {
        if (c + 2 < NCH) prefetch(c + 2, (c + 2) & 3);
        CP_COMMIT();
        CP_WAIT2();
        __syncthreads();

        const float* AsS = As + (c & 3) * AD_ASZ;
        const float* BsS = Bs + (c & 3) * AD_BSZ;
        #pragma unroll
        for (int g = 0; g < 2; g++) {
            unsigned a[4];
            a[0] = __float_as_uint(AsS[(m0 + lr    ) * 20 + g * 8 + kc    ]);
            a[1] = __float_as_uint(AsS[(m0 + lr + 8) * 20 + g * 8 + kc    ]);
            a[2] = __float_as_uint(AsS[(m0 + lr    ) * 20 + g * 8 + kc + 4]);
            a[3] = __float_as_uint(AsS[(m0 + lr + 8) * 20 + g * 8 + kc + 4]);
            #pragma unroll
            for (int j = 0; j < 13; j++) {
                unsigned b[2];
                b[0] = __float_as_uint(BsS[(nb0 + 8 * j + lr) * 20 + g * 8 + kc    ]);
                b[1] = __float_as_uint(BsS[(nb0 + 8 * j + lr) * 20 + g * 8 + kc + 4]);
                mma8(acc[j], a, b);
            }
        }
    }

    #pragma unroll
    for (int half = 0; half < 2; half++) {
        int r = rt + m0 + lr + half * 8;
        size_t rb = (size_t)r * 204;
        #pragma unroll
        for (int j = 0; j < 13; j++) {
            int u = nb0 + 8 * j + 2 * kc;
            if (u < 204) {
                float2 xv = *(const float2*)(x + rb + u);
                float va = acc[j][half * 2]     * s + sh + xv.x;
                float vb = acc[j][half * 2 + 1] * s + sh + xv.y;
                *(float2*)(out + rb + u) =
                    make_float2(rna_f(fmaxf(va, 0.f)), rna_f(fmaxf(vb, 0.f)));
            }
        }
    }
}

// ============================================================================
// attn_mma (R5 + batch offset)
// ============================================================================
#define AT_QSZ (64 * 20)
#define AT_SMEM (4 * 2 * AT_QSZ * 4)

__global__ __launch_bounds__(256, 4)
void attn_mma(const float* __restrict__ qk, float* __restrict__ part, int nbase)
{
    extern __shared__ float sm[];
    float* Qs = sm;
    float* Ks = sm + 4 * AT_QSZ;

    const int hh = blockIdx.x, n = blockIdx.y + nbase, z = blockIdx.z;
    const int cc0 = z * 4;
    const int tid = threadIdx.x, lane = tid & 31, warp = tid >> 5;
    const int wm = warp & 3, wn = warp >> 2;
    const int m0 = wm * 16, nb0 = wn * 32;
    const int lr = lane >> 2, kc = lane & 3;

    const float* qbase = qk + ((size_t)n * OQKV + hh * QKd) * Pp;
    const float* kbase = qk + ((size_t)n * OQKV + Hh * QKd + hh * QKd) * Pp;

    const int arow = tid >> 2, agrp = tid & 3;
    const int NCH = 52;

    float acc[4][4];
    #pragma unroll
    for (int j = 0; j < 4; j++)
        #pragma unroll
        for (int q = 0; q < 4; q++) acc[j][q] = 0.f;

    auto prefetch = [&](int c, int stage) {
        int ci = cc0 + (c / 13);
        int vb = (c % 13) * 16;
        int v = vb + agrp * 4;
        int ok = (v < 204);
        const float* qs = qbase + (size_t)ci * Pp + (size_t)arow * 204 + v;
        const float* ks = kbase + (size_t)ci * Pp + (size_t)arow * 204 + v;
        cpa16z(smem_u32(&Qs[stage * AT_QSZ + arow * 20 + agrp * 4]), ok ? qs : qk, ok ? 16 : 0);
        cpa16z(smem_u32(&Ks[stage * AT_QSZ + arow * 20 + agrp * 4]), ok ? ks : qk, ok ? 16 : 0);
    };

    prefetch(0, 0); CP_COMMIT();
    prefetch(1, 1); CP_COMMIT();

    for (int c = 0; c < NCH; c++) {
        if (c + 2 < NCH) prefetch(c + 2, (c + 2) & 3);
        CP_COMMIT();
        CP_WAIT2();
        __syncthreads();

        const float* QsS = Qs + (c & 3) * AT_QSZ;
        const float* KsS = Ks + (c & 3) * AT_QSZ;
        #pragma unroll
        for (int g = 0; g < 2; g++) {
            unsigned a[4];
            a[0] = __float_as_uint(QsS[(m0 + lr    ) * 20 + g * 8 + kc    ]);
            a[1] = __float_as_uint(QsS[(m0 + lr + 8) * 20 + g * 8 + kc    ]);
            a[2] = __float_as_uint(QsS[(m0 + lr    ) * 20 + g * 8 + kc + 4]);
            a[3] = __float_as_uint(QsS[(m0 + lr + 8) * 20 + g * 8 + kc + 4]);
            #pragma unroll
            for (int j = 0; j < 4; j++) {
                unsigned b[2];
                b[0] = __float_as_uint(KsS[(nb0 + 8 * j + lr) * 20 + g * 8 + kc    ]);
                b[1] = __float_as_uint(KsS[(nb0 + 8 * j + lr) * 20 + g * 8 + kc + 4]);
                mma8(acc[j], a, b);
            }
        }
    }

    float* pb = part + (((size_t)z * Nn + n) * Hh + hh) * 4096;
    #pragma unroll
    for (int half = 0; half < 2; half++) {
        int t = m0 + lr + half * 8;
        #pragma unroll
        for (int j = 0; j < 4; j++) {
            int q = nb0 + 8 * j + 2 * kc;
            *(float2*)(pb + (size_t)t * 64 + q) =
                make_float2(acc[j][half * 2], acc[j][half * 2 + 1]);
        }
    }
}

__global__ void attn_combine_kernel(const float* __restrict__ part,
                                    const float* __restrict__ alphas,
                                    const float* __restrict__ att1s,
                                    float* __restrict__ att, int nbase)
{
    int idx = blockIdx.x * blockDim.x + threadIdx.x;
    const int seg_total = NB * Hh * Tt * Tt;
    if (idx >= seg_total) return;
    int tq = idx & (Tt * Tt - 1);
    int rest = idx >> 12;
    int h = rest % Hh;
    int n = nbase + rest / Hh;
    const int total = Nn * Hh * Tt * Tt;
    size_t gi = (((size_t)n * Hh + h) << 12) + tq;
    float p = part[gi] + part[(size_t)total + gi]
            + part[2 * (size_t)total + gi] + part[3 * (size_t)total + gi];
    const float inv = 1.0f / (float)(QKd * Vv);
    att[gi] = rna_f(tanhf(p * inv) * alphas[h] + att1s[(size_t)h * Tt * Tt + tq]);
}

// ============================================================================
// z_mma (R5 + batch offset)
// ============================================================================
#define ZM_ASZ (16 * 72)
#define ZM_BSZ (16 * 232)
#define ZM_SMEM (4 * (ZM_ASZ + ZM_BSZ) * 4)

__global__ __launch_bounds__(256, 2)
void z_mma(const float* __restrict__ G2, const float* __restrict__ att,
           const float* __restrict__ g,
           const float* __restrict__ on_b, const float* __restrict__ on_g,
           const float* __restrict__ on_bb, const float* __restrict__ on_m,
           const float* __restrict__ on_v,
           float* __restrict__ out, int nbase)
{
    extern __shared__ float sm[];
    float* As = sm;
    float* Bs = sm + 4 * ZM_ASZ;

    const int cch = blockIdx.x, n = blockIdx.y + nbase;
    const int tid = threadIdx.x, lane = tid & 31, warp = tid >> 5;
    const int wm = warp & 3, wn = warp >> 2;
    const int m0 = wm * 16, nb0 = wn * 104;
    const int lr = lane >> 2, kc = lane & 3;

    float acc[13][4];
    #pragma unroll
    for (int j = 0; j < 13; j++)
        #pragma unroll
        for (int q = 0; q < 4; q++) acc[j][q] = 0.f;

    const int NCH = 12;

    auto prefetch = [&](int c, int stage) {
        int s  = c >> 2;
        int tb = (c & 3) * 16;
        const float* gb = G2 + ((size_t)n * HC + s * 64 + cch) * Pp;
        float* BsS = Bs + stage * ZM_BSZ;
        #pragma unroll
        for (int i = 0; i < 4; i++) {
            int e = tid + 256 * i;
            if (e < 832) {
                int trow = e / 52, grp = e % 52;
                int ok = (grp < 51);
                cpa16z(smem_u32(&BsS[trow * 232 + grp * 4]),
                       ok ? (gb + (size_t)(tb + trow) * 204 + grp * 4) : gb, ok ? 16 : 0);
            }
        }
        float* AsS = As + stage * ZM_ASZ;
        int trow = tid >> 4, grp = tid & 15;
        cpa16(smem_u32(&AsS[trow * 72 + grp * 4]),
              att + ((size_t)(n * Hh + s)) * 4096 + (size_t)(tb + trow) * 64 + grp * 4);
    };

    prefetch(0, 0); CP_COMMIT();
    prefetch(1, 1); CP_COMMIT();

    for (int c = 0; c < NCH; c++) {
        if (c + 2 < NCH) prefetch(c + 2, (c + 2) & 3);
        CP_COMMIT();
        CP_WAIT2();
        __syncthreads();

        const float* AsS = As + (c & 3) * ZM_ASZ;
        const float* BsS = Bs + (c & 3) * ZM_BSZ;
        #pragma unroll
        for (int g8 = 0; g8 < 2; g8++) {
            unsigned a[4];
            a[0] = __float_as_uint(AsS[(g8 * 8 + kc    ) * 72 + m0 + lr    ]);
            a[1] = __float_as_uint(AsS[(g8 * 8 + kc    ) * 72 + m0 + lr + 8]);
            a[2] = __float_as_uint(AsS[(g8 * 8 + kc + 4) * 72 + m0 + lr    ]);
            a[3] = __float_as_uint(AsS[(g8 * 8 + kc + 4) * 72 + m0 + lr + 8]);
            #pragma unroll
            for (int j = 0; j < 13; j++) {
                unsigned b[2];
                b[0] = __float_as_uint(BsS[(g8 * 8 + kc    ) * 232 + nb0 + 8 * j + lr]);
                b[1] = __float_as_uint(BsS[(g8 * 8 + kc + 4) * 232 + nb0 + 8 * j + lr]);
                mma8(acc[j], a, b);
            }
        }
    }

    const float sbn = on_g[cch] * rsqrtf(on_v[cch] + 1e-5f);
    const float sh  = on_bb[cch] - on_m[cch] * sbn + on_b[cch] * sbn;
    const float* gres = g + ((size_t)n * Cc + cch) * Pp;
    float* zb = out + ((size_t)n * Cc + cch) * Pp;

    #pragma unroll
    for (int half = 0; half < 2; half++) {
        int q = m0 + lr + half * 8;
        #pragma unroll
        for (int j = 0; j < 13; j++) {
            int v = nb0 + 8 * j + 2 * kc;
            if (v < 204) {
                float2 rv = *(const float2*)(gres + (size_t)q * 204 + v);
                float va = acc[j][half * 2]     * sbn + sh + rv.x;
                float vb = acc[j][half * 2 + 1] * sbn + sh + rv.y;
                va = (va > 0.f) ? va : 0.1f * va;
                vb = (vb > 0.f) ? vb : 0.1f * vb;
                *(float2*)(zb + (size_t)q * 204 + v) = make_float2(rna_f(va), rna_f(vb));
            }
        }
    }
}

// ---------------- launch: 2-segment skewed pipeline on ONE extra stream ----------------
extern "C" void kernel_launch(void* const* d_in, const int* in_sizes, int n_in,
                              void* d_out, int out_size)
{
    const float* x      = (const float*)d_in[0];
    const float* A      = (const float*)d_in[1];
    const float* gcn_w  = (const float*)d_in[2];
    const float* gcn_b  = (const float*)d_in[3];
    const float* gcn_g  = (const float*)d_in[4];
    const float* gcn_bb = (const float*)d_in[5];
    const float* gcn_m  = (const float*)d_in[6];
    const float* gcn_v  = (const float*)d_in[7];
    const float* pe     = (const float*)d_in[8];
    const float* qkv_w  = (const float*)d_in[9];
    const float* qkv_b  = (const float*)d_in[10];
    const float* alphas = (const float*)d_in[11];
    const float* att1s  = (const float*)d_in[12];
    const float* on_w   = (const float*)d_in[13];
    const float* on_b   = (const float*)d_in[14];
    const float* on_g   = (const float*)d_in[15];
    const float* on_bb  = (const float*)d_in[16];
    const float* on_m   = (const float*)d_in[17];
    const float* on_v   = (const float*)d_in[18];
    const float* ff_w   = (const float*)d_in[19];
    const float* ff_b   = (const float*)d_in[20];
    const float* ff_g   = (const float*)d_in[21];
    const float* ff_bb  = (const float*)d_in[22];
    const float* ff_m   = (const float*)d_in[23];
    const float* ff_v   = (const float*)d_in[24];
    float* out = (float*)d_out;

    float *ph, *pg, *pqk, *pwpe, *patt, *pattp, *pG2, *pwt, *pA2;
    cudaGetSymbolAddress((void**)&ph,    d_h);
    cudaGetSymbolAddress((void**)&pg,    d_g);
    cudaGetSymbolAddress((void**)&pqk,   d_qk);
    cudaGetSymbolAddress((void**)&pwpe,  d_wpe);
    cudaGetSymbolAddress((void**)&patt,  d_att);
    cudaGetSymbolAddress((void**)&pattp, d_attp);
    cudaGetSymbolAddress((void**)&pG2,   d_G2);
    cudaGetSymbolAddress((void**)&pwt,   d_wt);
    cudaGetSymbolAddress((void**)&pA2,   d_A2);

    static int init_done = 0;
    static cudaStream_t s2;
    static cudaEvent_t e1, e2, e3, e4, e5, e6, evS;
    if (!init_done) {
        cudaFuncSetAttribute(conv_mma<MODE_BIAS, 0>, cudaFuncAttributeMaxDynamicSharedMemorySize, CV_SMEM);
        cudaFuncSetAttribute(conv_mma<MODE_BIAS, 1>, cudaFuncAttributeMaxDynamicSharedMemorySize, CV_SMEM);
        cudaFuncSetAttribute(conv_mma<MODE_ADD2D, 1>, cudaFuncAttributeMaxDynamicSharedMemorySize, CV_SMEM);
        cudaFuncSetAttribute(conv_mma<MODE_NONE, 1>, cudaFuncAttributeMaxDynamicSharedMemorySize, CV_SMEM);
        cudaFuncSetAttribute(conv_mma<MODE_BN_RES_LEAKY, 0>, cudaFuncAttributeMaxDynamicSharedMemorySize, CV_SMEM);
        cudaFuncSetAttribute(adj_mma, cudaFuncAttributeMaxDynamicSharedMemorySize, AD_SMEM);
        cudaFuncSetAttribute(attn_mma, cudaFuncAttributeMaxDynamicSharedMemorySize, AT_SMEM);
        cudaFuncSetAttribute(z_mma, cudaFuncAttributeMaxDynamicSharedMemorySize, ZM_SMEM);
        cudaStreamCreateWithFlags(&s2, cudaStreamNonBlocking);
        cudaEventCreateWithFlags(&e1, cudaEventDisableTiming);
        cudaEventCreateWithFlags(&e2, cudaEventDisableTiming);
        cudaEventCreateWithFlags(&e3, cudaEventDisableTiming);
        cudaEventCreateWithFlags(&e4, cudaEventDisableTiming);
        cudaEventCreateWithFlags(&e5, cudaEventDisableTiming);
        cudaEventCreateWithFlags(&e6, cudaEventDisableTiming);
        cudaEventCreateWithFlags(&evS, cudaEventDisableTiming);
        init_done = 1;
    }

    dim3 blk(256);

    // ---- Stream 0: segment A (n 0..15), plus prep + wpe ----
    prep_kernel<<<(4096 + 6144 + 4096 + 12288 + 208 * 208 + 255) / 256, blk>>>(
        gcn_w, qkv_w, ff_w, on_w, A, pwt, pA2);

    // wpe (small; ahead of K1a so both segments' K3 are covered by stage ordering)
    conv_mma<MODE_BIAS, 0><<<dim3(Pp / 256, 2, 1), blk, CV_SMEM>>>(
        pe, pwt + WT_QKV, qkv_b, nullptr, nullptr, nullptr, nullptr, nullptr, nullptr,
        pwpe, Cc, OQKV, 0);

    // S0 stage 1: K1a
    conv_mma<MODE_BIAS, 1><<<dim3(Pp / 256, 1, NB), blk, CV_SMEM>>>(
        x, pwt + WT_GCN, gcn_b, nullptr, nullptr, nullptr, nullptr, nullptr, nullptr,
        ph, Cc, Cc, 0);
    cudaEventRecord(e1, 0);

    // S0 stage 2: K2a
    adj_mma<<<dim3((NB * Cc * Tt) / 64, 1, 1), blk, AD_SMEM>>>(
        ph, pA2, x, gcn_g, gcn_bb, gcn_m, gcn_v, pg, 0);
    cudaEventRecord(e2, 0);

    // S0 stage 3: K3a
    conv_mma<MODE_ADD2D, 1><<<dim3(Pp / 256, 2, NB), blk, CV_SMEM>>>(
        pg, pwt + WT_QKV, nullptr, pwpe, nullptr, nullptr, nullptr, nullptr, nullptr,
        pqk, Cc, OQKV, 0);
    cudaEventRecord(e3, 0);

    // S0 stage 4: attn_a + combine_a
    attn_mma<<<dim3(Hh, NB, 4), blk, AT_SMEM>>>(pqk, pattp, 0);
    attn_combine_kernel<<<(NB * Hh * Tt * Tt + 255) / 256, blk>>>(pattp, alphas, att1s, patt, 0);
    cudaEventRecord(e4, 0);

    // S0 stage 5: K5a
    conv_mma<MODE_NONE, 1><<<dim3(Pp / 256, 3, NB), blk, CV_SMEM>>>(
        pg, pwt + WT_W2, nullptr, nullptr, nullptr, nullptr, nullptr, nullptr, nullptr,
        pG2, Cc, HC, 0);
    cudaEventRecord(e5, 0);

    // S0 stage 6: K6a
    z_mma<<<dim3(Cc, NB), blk, ZM_SMEM>>>(
        pG2, patt, pg, on_b, on_g, on_bb, on_m, on_v, ph, 0);
    cudaEventRecord(e6, 0);

    // S0 stage 7: K7a
    conv_mma<MODE_BN_RES_LEAKY, 0><<<dim3(Pp / 256, 1, NB), blk, CV_SMEM>>>(
        ph, pwt + WT_FF, ff_b, nullptr, pg, ff_g, ff_bb, ff_m, ff_v,
        out, Cc, Cc, 0);

    // ---- Stream s2: segment B (n 16..31), one stage behind ----
    cudaStreamWaitEvent(s2, e1, 0);   // prep + K1a done -> start K1b beside K2a
    conv_mma<MODE_BIAS, 1><<<dim3(Pp / 256, 1, NB), blk, CV_SMEM, s2>>>(
        x, pwt + WT_GCN, gcn_b, nullptr, nullptr, nullptr, nullptr, nullptr, nullptr,
        ph, Cc, Cc, NB);

    cudaStreamWaitEvent(s2, e2, 0);
    adj_mma<<<dim3((NB * Cc * Tt) / 64, 1, 1), blk, AD_SMEM, s2>>>(
        ph, pA2, x, gcn_g, gcn_bb, gcn_m, gcn_v, pg, NB * Cc * Tt);

    cudaStreamWaitEvent(s2, e3, 0);   // K3a (after wpe on S0) done
    conv_mma<MODE_ADD2D, 1><<<dim3(Pp / 256, 2, NB), blk, CV_SMEM, s2>>>(
        pg, pwt + WT_QKV, nullptr, pwpe, nullptr, nullptr, nullptr, nullptr, nullptr,
        pqk, Cc, OQKV, NB);

    cudaStreamWaitEvent(s2, e4, 0);
    attn_mma<<<dim3(Hh, NB, 4), blk, AT_SMEM, s2>>>(pqk, pattp, NB);
    attn_combine_kernel<<<(NB * Hh * Tt * Tt + 255) / 256, blk, 0, s2>>>(
        pattp, alphas, att1s, patt, NB);

    cudaStreamWaitEvent(s2, e5, 0);
    conv_mma<MODE_NONE, 1><<<dim3(Pp / 256, 3, NB), blk, CV_SMEM, s2>>>(
        pg, pwt + WT_W2, nullptr, nullptr, nullptr, nullptr, nullptr, nullptr, nullptr,
        pG2, Cc, HC, NB);

    cudaStreamWaitEvent(s2, e6, 0);
    z_mma<<<dim3(Cc, NB), blk, ZM_SMEM, s2>>>(
        pG2, patt, pg, on_b, on_g, on_bb, on_m, on_v, ph, NB);

    conv_mma<MODE_BN_RES_LEAKY, 0><<<dim3(Pp / 256, 1, NB), blk, CV_SMEM, s2>>>(
        ph, pwt + WT_FF, ff_b, nullptr, pg, ff_g, ff_bb, ff_m, ff_v,
        out, Cc, Cc, NB);
    cudaEventRecord(evS, s2);

    // join
    cudaStreamWaitEvent(0, evS, 0);
}

// round 11
// speedup vs baseline: 1.1163x; 1.0012x over previous
#include <cuda_runtime.h>
#include <math.h>
#include <stdint.h>

// Problem constants
#define Nn   32
#define Cc   64
#define Tt   64
#define Vv   204
#define Hh   3
#define QKd  16
#define Pp   13056
#define OQKV 96
#define HC   192

#define NB   16   // batches per segment (2 segments)

// ---------------- scratch ----------------
__device__ float d_h   [(size_t)Nn * Cc * Pp + 64];
__device__ float d_g   [(size_t)Nn * Cc * Pp + 64];
__device__ float d_qk  [(size_t)Nn * OQKV * Pp + 64];
__device__ float d_wpe [(size_t)OQKV * Pp];
__device__ float d_att [(size_t)Nn * Hh * Tt * Tt];
__device__ float d_attp[(size_t)4 * Nn * Hh * Tt * Tt];
__device__ float d_G2  [(size_t)Nn * HC * Pp + 64];
__device__ float d_wt  [4096 + 6144 + 4096 + 12288];  // tf32: gcn | qkv | ff | w2
__device__ float d_A2  [208 * 208];

#define WT_GCN 0
#define WT_QKV 4096
#define WT_FF  10240
#define WT_W2  14336

enum { MODE_BIAS = 0, MODE_ADD2D = 1, MODE_BN_RES_LEAKY = 2, MODE_NONE = 3 };

// ---------------- helpers ----------------
__device__ __forceinline__ unsigned cvt_tf32(float f) {
    unsigned u;
    asm("cvt.rna.tf32.f32 %0, %1;" : "=r"(u) : "f"(f));
    return u;
}
__device__ __forceinline__ float rna_f(float f) { return __uint_as_float(cvt_tf32(f)); }

__device__ __forceinline__ void mma8(float* d, const unsigned* a, const unsigned* b) {
    asm volatile(
        "mma.sync.aligned.m16n8k8.row.col.f32.tf32.tf32.f32 "
        "{%0,%1,%2,%3},{%4,%5,%6,%7},{%8,%9},{%0,%1,%2,%3};"
        : "+f"(d[0]), "+f"(d[1]), "+f"(d[2]), "+f"(d[3])
        : "r"(a[0]), "r"(a[1]), "r"(a[2]), "r"(a[3]), "r"(b[0]), "r"(b[1]));
}

__device__ __forceinline__ uint32_t smem_u32(const void* p) {
    return (uint32_t)__cvta_generic_to_shared(p);
}
__device__ __forceinline__ void cpa16(uint32_t dst, const void* src) {
    asm volatile("cp.async.cg.shared.global [%0],[%1],16;" :: "r"(dst), "l"(src));
}
__device__ __forceinline__ void cpa16z(uint32_t dst, const void* src, int sz) {
    asm volatile("cp.async.cg.shared.global [%0],[%1],16,%2;" :: "r"(dst), "l"(src), "r"(sz));
}
#define CP_COMMIT() asm volatile("cp.async.commit_group;")
#define CP_WAIT2()  asm volatile("cp.async.wait_group 2;")

// ============================================================================
// prep
// ============================================================================
__global__ void prep_kernel(const float* __restrict__ gcn_w, const float* __restrict__ qkv_w,
                            const float* __restrict__ ff_w, const float* __restrict__ on_w,
                            const float* __restrict__ A,
                            float* __restrict__ wt, float* __restrict__ A2)
{
    int i = blockIdx.x * 256 + threadIdx.x;
    if (i < 4096) { wt[WT_GCN + i] = rna_f(gcn_w[i]); return; }
    i -= 4096;
    if (i < 6144) { wt[WT_QKV + i] = rna_f(qkv_w[i]); return; }
    i -= 6144;
    if (i < 4096) { wt[WT_FF + i] = rna_f(ff_w[i]); return; }
    i -= 4096;
    if (i < 12288) {
        int o = i >> 6, cc = i & 63;
        int s = o >> 6, c = o & 63;
        wt[WT_W2 + i] = rna_f(on_w[(size_t)c * HC + s * 64 + cc]);
        return;
    }
    i -= 12288;
    if (i < 208 * 208) {
        int u = i / 208, v = i % 208;
        A2[i] = (u < 204 && v < 204) ? rna_f(A[(size_t)u * 204 + v]) : 0.f;
    }
}

// ============================================================================
// conv_mma (R5 + batch offset)
// ============================================================================
#define CV_ASZ (64 * 20)
#define CV_BSZ (16 * 264)
#define CV_SMEM (4 * (CV_ASZ + CV_BSZ) * 4)

template <int MODE, int ROUND>
__global__ __launch_bounds__(256, 2)
void conv_mma(const float* __restrict__ in, const float* __restrict__ Wt,
              const float* __restrict__ bias, const float* __restrict__ add2d,
              const float* __restrict__ res,
              const float* __restrict__ bng, const float* __restrict__ bnb,
              const float* __restrict__ bnm, const float* __restrict__ bnv,
              float* __restrict__ out, int Kc, int Oc, int nbase)
{
    extern __shared__ float sm[];
    float* As = sm;
    float* Bs = sm + 4 * CV_ASZ;

    const int n  = blockIdx.z + nbase;
    const int pt = blockIdx.x * 256;
    const int ot = blockIdx.y * 64;
    const int tid = threadIdx.x, lane = tid & 31, warp = tid >> 5;
    const int wm = warp & 1, wn = warp >> 1;
    const int m0 = wm * 32, n0 = wn * 64;
    const int lr = lane >> 2, kc = lane & 3;

    const float* inN = in + (size_t)n * Kc * Pp + pt;
    const int NCH = Kc >> 4;

    float acc[2][8][4];
    #pragma unroll
    for (int f = 0; f < 2; f++)
        #pragma unroll
        for (int j = 0; j < 8; j++)
            #pragma unroll
            for (int q = 0; q < 4; q++) acc[f][j][q] = 0.f;

    auto prefetch = [&](int c, int stage) {
        float* BsS = Bs + stage * CV_BSZ;
        const float* bsrc = inN + (size_t)(c * 16) * Pp;
        #pragma unroll
        for (int i = 0; i < 4; i++) {
            int e = tid + 256 * i;
            int k = e >> 6, grp = e & 63;
            cpa16(smem_u32(&BsS[k * 264 + grp * 4]), bsrc + (size_t)k * Pp + grp * 4);
        }
        float* AsS = As + stage * CV_ASZ;
        int arow = tid >> 2, agrp = tid & 3;
        int o = ot + arow;
        int ok = (o < Oc);
        cpa16z(smem_u32(&AsS[arow * 20 + agrp * 4]),
               ok ? (Wt + (size_t)o * Kc + c * 16 + agrp * 4) : Wt, ok ? 16 : 0);
    };

    prefetch(0, 0); CP_COMMIT();
    if (NCH > 1) prefetch(1, 1);
    CP_COMMIT();

    for (int c = 0; c < NCH; c++) {
        if (c + 2 < NCH) prefetch(c + 2, (c + 2) & 3);
        CP_COMMIT();
        CP_WAIT2();
        __syncthreads();

        const float* AsS = As + (c & 3) * CV_ASZ;
        const float* BsS = Bs + (c & 3) * CV_BSZ;
        #pragma unroll
        for (int g = 0; g < 2; g++) {
            unsigned a[2][4];
            #pragma unroll
            for (int f = 0; f < 2; f++) {
                a[f][0] = __float_as_uint(AsS[(m0 + f * 16 + lr    ) * 20 + g * 8 + kc    ]);
                a[f][1] = __float_as_uint(AsS[(m0 + f * 16 + lr + 8) * 20 + g * 8 + kc    ]);
                a[f][2] = __float_as_uint(AsS[(m0 + f * 16 + lr    ) * 20 + g * 8 + kc + 4]);
                a[f][3] = __float_as_uint(AsS[(m0 + f * 16 + lr + 8) * 20 + g * 8 + kc + 4]);
            }
            #pragma unroll
            for (int j = 0; j < 8; j++) {
                unsigned b[2];
                b[0] = __float_as_uint(BsS[(g * 8 + kc    ) * 264 + n0 + 8 * j + lr]);
                b[1] = __float_as_uint(BsS[(g * 8 + kc + 4) * 264 + n0 + 8 * j + lr]);
                mma8(acc[0][j], a[0], b);
                mma8(acc[1][j], a[1], b);
            }
        }
    }

    #pragma unroll
    for (int f = 0; f < 2; f++) {
        #pragma unroll
        for (int half = 0; half < 2; half++) {
            int o = ot + m0 + f * 16 + lr + half * 8;
            if (o >= Oc) continue;
            size_t obase = ((size_t)n * Oc + o) * Pp;
            if (MODE == MODE_NONE) {
                #pragma unroll
                for (int j = 0; j < 8; j++) {
                    int p = pt + n0 + 8 * j + 2 * kc;
                    float va = acc[f][j][half * 2], vb = acc[f][j][half * 2 + 1];
                    if (ROUND) { va = rna_f(va); vb = rna_f(vb); }
                    *(float2*)(out + obase + p) = make_float2(va, vb);
                }
            } else if (MODE == MODE_BIAS) {
                float b = bias[o];
                #pragma unroll
                for (int j = 0; j < 8; j++) {
                    int p = pt + n0 + 8 * j + 2 * kc;
                    float va = acc[f][j][half * 2] + b, vb = acc[f][j][half * 2 + 1] + b;
                    if (ROUND) { va = rna_f(va); vb = rna_f(vb); }
                    *(float2*)(out + obase + p) = make_float2(va, vb);
                }
            } else if (MODE == MODE_ADD2D) {
                size_t abase = (size_t)o * Pp;
                #pragma unroll
                for (int j = 0; j < 8; j++) {
                    int p = pt + n0 + 8 * j + 2 * kc;
                    float2 av = *(const float2*)(add2d + abase + p);
                    float va = acc[f][j][half * 2] + av.x, vb = acc[f][j][half * 2 + 1] + av.y;
                    if (ROUND) { va = rna_f(va); vb = rna_f(vb); }
                    *(float2*)(out + obase + p) = make_float2(va, vb);
                }
            } else {
                float s  = bng[o] * rsqrtf(bnv[o] + 1e-5f);
                float sh = bnb[o] - bnm[o] * s + bias[o] * s;
                #pragma unroll
                for (int j = 0; j < 8; j++) {
                    int p = pt + n0 + 8 * j + 2 * kc;
                    float2 rv = *(const float2*)(res + obase + p);
                    float va = acc[f][j][half * 2]     * s + sh + rv.x;
                    float vb = acc[f][j][half * 2 + 1] * s + sh + rv.y;
                    va = (va > 0.f) ? va : 0.1f * va;
                    vb = (vb > 0.f) ? vb : 0.1f * vb;
                    if (ROUND) { va = rna_f(va); vb = rna_f(vb); }
                    *(float2*)(out + obase + p) = make_float2(va, vb);
                }
            }
        }
    }
}

// ============================================================================
// adj_mma (R5 + row offset)
// ============================================================================
#define AD_ASZ (64 * 20)
#define AD_BSZ (208 * 20)
#define AD_SMEM (4 * (AD_ASZ + AD_BSZ) * 4)

__global__ __launch_bounds__(256, 2)
void adj_mma(const float* __restrict__ h, const float* __restrict__ A2,
             const float* __restrict__ x,
             const float* __restrict__ bng, const float* __restrict__ bnb,
             const float* __restrict__ bnm, const float* __restrict__ bnv,
             float* __restrict__ out, int rbase)
{
    extern __shared__ float sm[];
    float* As = sm;
    float* Bs = sm + 4 * AD_ASZ;

    const int rt = blockIdx.x * 64 + rbase;
    const int tid = threadIdx.x, lane = tid & 31, warp = tid >> 5;
    const int wm = warp & 3, wn = warp >> 2;
    const int m0 = wm * 16, nb0 = wn * 104;
    const int lr = lane >> 2, kc = lane & 3;

    const int ch  = (rt >> 6) & 63;
    const float s  = bng[ch] * rsqrtf(bnv[ch] + 1e-5f);
    const float sh = bnb[ch] - bnm[ch] * s;

    float acc[13][4];
    #pragma unroll
    for (int j = 0; j < 13; j++)
        #pragma unroll
        for (int q = 0; q < 4; q++) acc[j][q] = 0.f;

    const int arow = tid >> 2, agrp = tid & 3;
    const int NCH = 13;

    auto prefetch = [&](int c, int stage) {
        float* BsS = Bs + stage * AD_BSZ;
        #pragma unroll
        for (int i = 0; i < 4; i++) {
            int e = tid + 256 * i;
            if (e < 832) {
                int u = e >> 2, grp = e & 3;
                cpa16(smem_u32(&BsS[u * 20 + grp * 4]), A2 + (size_t)u * 208 + c * 16 + grp * 4);
            }
        }
        float* AsS = As + stage * AD_ASZ;
        cpa16(smem_u32(&AsS[arow * 20 + agrp * 4]),
              h + (size_t)(rt + arow) * 204 + c * 16 + agrp * 4);
    };

    prefetch(0, 0); CP_COMMIT();
    prefetch(1, 1); CP_COMMIT();

    for (int c = 0; c < NCH; c++) {
        if (c + 2 < NCH) prefetch(c + 2, (c + 2) & 3);
        CP_COMMIT();
        CP_WAIT2();
        __syncthreads();

        const float* AsS = As + (c & 3) * AD_ASZ;
        const float* BsS = Bs + (c & 3) * AD_BSZ;
        #pragma unroll
        for (int g = 0; g < 2; g++) {
            unsigned a[4];
            a[0] = __float_as_uint(AsS[(m0 + lr    ) * 20 + g * 8 + kc    ]);
            a[1] = __float_as_uint(AsS[(m0 + lr + 8) * 20 + g * 8 + kc    ]);
            a[2] = __float_as_uint(AsS[(m0 + lr    ) * 20 + g * 8 + kc + 4]);
            a[3] = __float_as_uint(AsS[(m0 + lr + 8) * 20 + g * 8 + kc + 4]);
            #pragma unroll
            for (int j = 0; j < 13; j++) {
                unsigned b[2];
                b[0] = __float_as_uint(BsS[(nb0 + 8 * j + lr) * 20 + g * 8 + kc    ]);
                b[1] = __float_as_uint(BsS[(nb0 + 8 * j + lr) * 20 + g * 8 + kc + 4]);
                mma8(acc[j], a, b);
            }
        }
    }

    #pragma unroll
    for (int half = 0; half < 2; half++) {
        int r = rt + m0 + lr + half * 8;
        size_t rb = (size_t)r * 204;
        #pragma unroll
        for (int j = 0; j < 13; j++) {
            int u = nb0 + 8 * j + 2 * kc;
            if (u < 204) {
                float2 xv = *(const float2*)(x + rb + u);
                float va = acc[j][half * 2]     * s + sh + xv.x;
                float vb = acc[j][half * 2 + 1] * s + sh + xv.y;
                *(float2*)(out + rb + u) =
                    make_float2(rna_f(fmaxf(va, 0.f)), rna_f(fmaxf(vb, 0.f)));
            }
        }
    }
}

// ============================================================================
// attn_mma (R5 + batch offset)
// ============================================================================
#define AT_QSZ (64 * 20)
#define AT_SMEM (4 * 2 * AT_QSZ * 4)

__global__ __launch_bounds__(256, 4)
void attn_mma(const float* __restrict__ qk, float* __restrict__ part, int nbase)
{
    extern __shared__ float sm[];
    float* Qs = sm;
    float* Ks = sm + 4 * AT_QSZ;

    const int hh = blockIdx.x, n = blockIdx.y + nbase, z = blockIdx.z;
    const int cc0 = z * 4;
    const int tid = threadIdx.x, lane = tid & 31, warp = tid >> 5;
    const int wm = warp & 3, wn = warp >> 2;
    const int m0 = wm * 16, nb0 = wn * 32;
    const int lr = lane >> 2, kc = lane & 3;

    const float* qbase = qk + ((size_t)n * OQKV + hh * QKd) * Pp;
    const float* kbase = qk + ((size_t)n * OQKV + Hh * QKd + hh * QKd) * Pp;

    const int arow = tid >> 2, agrp = tid & 3;
    const int NCH = 52;

    float acc[4][4];
    #pragma unroll
    for (int j = 0; j < 4; j++)
        #pragma unroll
        for (int q = 0; q < 4; q++) acc[j][q] = 0.f;

    auto prefetch = [&](int c, int stage) {
        int ci = cc0 + (c / 13);
        int vb = (c % 13) * 16;
        int v = vb + agrp * 4;
        int ok = (v < 204);
        const float* qs = qbase + (size_t)ci * Pp + (size_t)arow * 204 + v;
        const float* ks = kbase + (size_t)ci * Pp + (size_t)arow * 204 + v;
        cpa16z(smem_u32(&Qs[stage * AT_QSZ + arow * 20 + agrp * 4]), ok ? qs : qk, ok ? 16 : 0);
        cpa16z(smem_u32(&Ks[stage * AT_QSZ + arow * 20 + agrp * 4]), ok ? ks : qk, ok ? 16 : 0);
    };

    prefetch(0, 0); CP_COMMIT();
    prefetch(1, 1); CP_COMMIT();

    for (int c = 0; c < NCH; c++) {
        if (c + 2 < NCH) prefetch(c + 2, (c + 2) & 3);
        CP_COMMIT();
        CP_WAIT2();
        __syncthreads();

        const float* QsS = Qs + (c & 3) * AT_QSZ;
        const float* KsS = Ks + (c & 3) * AT_QSZ;
        #pragma unroll
        for (int g = 0; g < 2; g++) {
            unsigned a[4];
            a[0] = __float_as_uint(QsS[(m0 + lr    ) * 20 + g * 8 + kc    ]);
            a[1] = __float_as_uint(QsS[(m0 + lr + 8) * 20 + g * 8 + kc    ]);
            a[2] = __float_as_uint(QsS[(m0 + lr    ) * 20 + g * 8 + kc + 4]);
            a[3] = __float_as_uint(QsS[(m0 + lr + 8) * 20 + g * 8 + kc + 4]);
            #pragma unroll
            for (int j = 0; j < 4; j++) {
                unsigned b[2];
                b[0] = __float_as_uint(KsS[(nb0 + 8 * j + lr) * 20 + g * 8 + kc    ]);
                b[1] = __float_as_uint(KsS[(nb0 + 8 * j + lr) * 20 + g * 8 + kc + 4]);
                mma8(acc[j], a, b);
            }
        }
    }

    float* pb = part + (((size_t)z * Nn + n) * Hh + hh) * 4096;
    #pragma unroll
    for (int half = 0; half < 2; half++) {
        int t = m0 + lr + half * 8;
        #pragma unroll
        for (int j = 0; j < 4; j++) {
            int q = nb0 + 8 * j + 2 * kc;
            *(float2*)(pb + (size_t)t * 64 + q) =
                make_float2(acc[j][half * 2], acc[j][half * 2 + 1]);
        }
    }
}

__global__ void attn_combine_kernel(const float* __restrict__ part,
                                    const float* __restrict__ alphas,
                                    const float* __restrict__ att1s,
                                    float* __restrict__ att, int nbase)
{
    int idx = blockIdx.x * blockDim.x + threadIdx.x;
    const int seg_total = NB * Hh * Tt * Tt;
    if (idx >= seg_total) return;
    int tq = idx & (Tt * Tt - 1);
    int rest = idx >> 12;
    int h = rest % Hh;
    int n = nbase + rest / Hh;
    const int total = Nn * Hh * Tt * Tt;
    size_t gi = (((size_t)n * Hh + h) << 12) + tq;
    float p = part[gi] + part[(size_t)total + gi]
            + part[2 * (size_t)total + gi] + part[3 * (size_t)total + gi];
    const float inv = 1.0f / (float)(QKd * Vv);
    att[gi] = rna_f(tanhf(p * inv) * alphas[h] + att1s[(size_t)h * Tt * Tt + tq]);
}

// ============================================================================
// z_mma (R5 + batch offset)
// ============================================================================
#define ZM_ASZ (16 * 72)
#define ZM_BSZ (16 * 232)
#define ZM_SMEM (4 * (ZM_ASZ + ZM_BSZ) * 4)

__global__ __launch_bounds__(256, 2)
void z_mma(const float* __restrict__ G2, const float* __restrict__ att,
           const float* __restrict__ g,
           const float* __restrict__ on_b, const float* __restrict__ on_g,
           const float* __restrict__ on_bb, const float* __restrict__ on_m,
           const float* __restrict__ on_v,
           float* __restrict__ out, int nbase)
{
    extern __shared__ float sm[];
    float* As = sm;
    float* Bs = sm + 4 * ZM_ASZ;

    const int cch = blockIdx.x, n = blockIdx.y + nbase;
    const int tid = threadIdx.x, lane = tid & 31, warp = tid >> 5;
    const int wm = warp & 3, wn = warp >> 2;
    const int m0 = wm * 16, nb0 = wn * 104;
    const int lr = lane >> 2, kc = lane & 3;

    float acc[13][4];
    #pragma unroll
    for (int j = 0; j < 13; j++)
        #pragma unroll
        for (int q = 0; q < 4; q++) acc[j][q] = 0.f;

    const int NCH = 12;

    auto prefetch = [&](int c, int stage) {
        int s  = c >> 2;
        int tb = (c & 3) * 16;
        const float* gb = G2 + ((size_t)n * HC + s * 64 + cch) * Pp;
        float* BsS = Bs + stage * ZM_BSZ;
        #pragma unroll
        for (int i = 0; i < 4; i++) {
            int e = tid + 256 * i;
            if (e < 832) {
                int trow = e / 52, grp = e % 52;
                int ok = (grp < 51);
                cpa16z(smem_u32(&BsS[trow * 232 + grp * 4]),
                       ok ? (gb + (size_t)(tb + trow) * 204 + grp * 4) : gb, ok ? 16 : 0);
            }
        }
        float* AsS = As + stage * ZM_ASZ;
        int trow = tid >> 4, grp = tid & 15;
        cpa16(smem_u32(&AsS[trow * 72 + grp * 4]),
              att + ((size_t)(n * Hh + s)) * 4096 + (size_t)(tb + trow) * 64 + grp * 4);
    };

    prefetch(0, 0); CP_COMMIT();
    prefetch(1, 1); CP_COMMIT();

    for (int c = 0; c < NCH; c++) {
        if (c + 2 < NCH) prefetch(c + 2, (c + 2) & 3);
        CP_COMMIT();
        CP_WAIT2();
        __syncthreads();

        const float* AsS = As + (c & 3) * ZM_ASZ;
        const float* BsS = Bs + (c & 3) * ZM_BSZ;
        #pragma unroll
        for (int g8 = 0; g8 < 2; g8++) {
            unsigned a[4];
            a[0] = __float_as_uint(AsS[(g8 * 8 + kc    ) * 72 + m0 + lr    ]);
            a[1] = __float_as_uint(AsS[(g8 * 8 + kc    ) * 72 + m0 + lr + 8]);
            a[2] = __float_as_uint(AsS[(g8 * 8 + kc + 4) * 72 + m0 + lr    ]);
            a[3] = __float_as_uint(AsS[(g8 * 8 + kc + 4) * 72 + m0 + lr + 8]);
            #pragma unroll
            for (int j = 0; j < 13; j++) {
                unsigned b[2];
                b[0] = __float_as_uint(BsS[(g8 * 8 + kc    ) * 232 + nb0 + 8 * j + lr]);
                b[1] = __float_as_uint(BsS[(g8 * 8 + kc + 4) * 232 + nb0 + 8 * j + lr]);
                mma8(acc[j], a, b);
            }
        }
    }

    const float sbn = on_g[cch] * rsqrtf(on_v[cch] + 1e-5f);
    const float sh  = on_bb[cch] - on_m[cch] * sbn + on_b[cch] * sbn;
    const float* gres = g + ((size_t)n * Cc + cch) * Pp;
    float* zb = out + ((size_t)n * Cc + cch) * Pp;

    #pragma unroll
    for (int half = 0; half < 2; half++) {
        int q = m0 + lr + half * 8;
        #pragma unroll
        for (int j = 0; j < 13; j++) {
            int v = nb0 + 8 * j + 2 * kc;
            if (v < 204) {
                float2 rv = *(const float2*)(gres + (size_t)q * 204 + v);
                float va = acc[j][half * 2]     * sbn + sh + rv.x;
                float vb = acc[j][half * 2 + 1] * sbn + sh + rv.y;
                va = (va > 0.f) ? va : 0.1f * va;
                vb = (vb > 0.f) ? vb : 0.1f * vb;
                *(float2*)(zb + (size_t)q * 204 + v) = make_float2(rna_f(va), rna_f(vb));
            }
        }
    }
}

// ---------------- launch: 2-segment skewed pipeline on ONE extra stream ----------------
extern "C" void kernel_launch(void* const* d_in, const int* in_sizes, int n_in,
                              void* d_out, int out_size)
{
    const float* x      = (const float*)d_in[0];
    const float* A      = (const float*)d_in[1];
    const float* gcn_w  = (const float*)d_in[2];
    const float* gcn_b  = (const float*)d_in[3];
    const float* gcn_g  = (const float*)d_in[4];
    const float* gcn_bb = (const float*)d_in[5];
    const float* gcn_m  = (const float*)d_in[6];
    const float* gcn_v  = (const float*)d_in[7];
    const float* pe     = (const float*)d_in[8];
    const float* qkv_w  = (const float*)d_in[9];
    const float* qkv_b  = (const float*)d_in[10];
    const float* alphas = (const float*)d_in[11];
    const float* att1s  = (const float*)d_in[12];
    const float* on_w   = (const float*)d_in[13];
    const float* on_b   = (const float*)d_in[14];
    const float* on_g   = (const float*)d_in[15];
    const float* on_bb  = (const float*)d_in[16];
    const float* on_m   = (const float*)d_in[17];
    const float* on_v   = (const float*)d_in[18];
    const float* ff_w   = (const float*)d_in[19];
    const float* ff_b   = (const float*)d_in[20];
    const float* ff_g   = (const float*)d_in[21];
    const float* ff_bb  = (const float*)d_in[22];
    const float* ff_m   = (const float*)d_in[23];
    const float* ff_v   = (const float*)d_in[24];
    float* out = (float*)d_out;

    float *ph, *pg, *pqk, *pwpe, *patt, *pattp, *pG2, *pwt, *pA2;
    cudaGetSymbolAddress((void**)&ph,    d_h);
    cudaGetSymbolAddress((void**)&pg,    d_g);
    cudaGetSymbolAddress((void**)&pqk,   d_qk);
    cudaGetSymbolAddress((void**)&pwpe,  d_wpe);
    cudaGetSymbolAddress((void**)&patt,  d_att);
    cudaGetSymbolAddress((void**)&pattp, d_attp);
    cudaGetSymbolAddress((void**)&pG2,   d_G2);
    cudaGetSymbolAddress((void**)&pwt,   d_wt);
    cudaGetSymbolAddress((void**)&pA2,   d_A2);

    static int init_done = 0;
    static cudaStream_t s2;
    static cudaEvent_t e1, e2, e3, e4, e5, e6, evS;
    if (!init_done) {
        cudaFuncSetAttribute(conv_mma<MODE_BIAS, 0>, cudaFuncAttributeMaxDynamicSharedMemorySize, CV_SMEM);
        cudaFuncSetAttribute(conv_mma<MODE_BIAS, 1>, cudaFuncAttributeMaxDynamicSharedMemorySize, CV_SMEM);
        cudaFuncSetAttribute(conv_mma<MODE_ADD2D, 1>, cudaFuncAttributeMaxDynamicSharedMemorySize, CV_SMEM);
        cudaFuncSetAttribute(conv_mma<MODE_NONE, 1>, cudaFuncAttributeMaxDynamicSharedMemorySize, CV_SMEM);
        cudaFuncSetAttribute(conv_mma<MODE_BN_RES_LEAKY, 0>, cudaFuncAttributeMaxDynamicSharedMemorySize, CV_SMEM);
        cudaFuncSetAttribute(adj_mma, cudaFuncAttributeMaxDynamicSharedMemorySize, AD_SMEM);
        cudaFuncSetAttribute(attn_mma, cudaFuncAttributeMaxDynamicSharedMemorySize, AT_SMEM);
        cudaFuncSetAttribute(z_mma, cudaFuncAttributeMaxDynamicSharedMemorySize, ZM_SMEM);
        cudaStreamCreateWithFlags(&s2, cudaStreamNonBlocking);
        cudaEventCreateWithFlags(&e1, cudaEventDisableTiming);
        cudaEventCreateWithFlags(&e2, cudaEventDisableTiming);
        cudaEventCreateWithFlags(&e3, cudaEventDisableTiming);
        cudaEventCreateWithFlags(&e4, cudaEventDisableTiming);
        cudaEventCreateWithFlags(&e5, cudaEventDisableTiming);
        cudaEventCreateWithFlags(&e6, cudaEventDisableTiming);
        cudaEventCreateWithFlags(&evS, cudaEventDisableTiming);
        init_done = 1;
    }

    dim3 blk(256);

    // ---- Stream 0: segment A (n 0..15), plus prep + wpe ----
    prep_kernel<<<(4096 + 6144 + 4096 + 12288 + 208 * 208 + 255) / 256, blk>>>(
        gcn_w, qkv_w, ff_w, on_w, A, pwt, pA2);

    // wpe (small; ahead of K1a so both segments' K3 are covered by stage ordering)
    conv_mma<MODE_BIAS, 0><<<dim3(Pp / 256, 2, 1), blk, CV_SMEM>>>(
        pe, pwt + WT_QKV, qkv_b, nullptr, nullptr, nullptr, nullptr, nullptr, nullptr,
        pwpe, Cc, OQKV, 0);

    // S0 stage 1: K1a
    conv_mma<MODE_BIAS, 1><<<dim3(Pp / 256, 1, NB), blk, CV_SMEM>>>(
        x, pwt + WT_GCN, gcn_b, nullptr, nullptr, nullptr, nullptr, nullptr, nullptr,
        ph, Cc, Cc, 0);
    cudaEventRecord(e1, 0);

    // S0 stage 2: K2a
    adj_mma<<<dim3((NB * Cc * Tt) / 64, 1, 1), blk, AD_SMEM>>>(
        ph, pA2, x, gcn_g, gcn_bb, gcn_m, gcn_v, pg, 0);
    cudaEventRecord(e2, 0);

    // S0 stage 3: K3a
    conv_mma<MODE_ADD2D, 1><<<dim3(Pp / 256, 2, NB), blk, CV_SMEM>>>(
        pg, pwt + WT_QKV, nullptr, pwpe, nullptr, nullptr, nullptr, nullptr, nullptr,
        pqk, Cc, OQKV, 0);
    cudaEventRecord(e3, 0);

    // S0 stage 4: attn_a + combine_a
    attn_mma<<<dim3(Hh, NB, 4), blk, AT_SMEM>>>(pqk, pattp, 0);
    attn_combine_kernel<<<(NB * Hh * Tt * Tt + 255) / 256, blk>>>(pattp, alphas, att1s, patt, 0);
    cudaEventRecord(e4, 0);

    // S0 stage 5: K5a
    conv_mma<MODE_NONE, 1><<<dim3(Pp / 256, 3, NB), blk, CV_SMEM>>>(
        pg, pwt + WT_W2, nullptr, nullptr, nullptr, nullptr, nullptr, nullptr, nullptr,
        pG2, Cc, HC, 0);
    cudaEventRecord(e5, 0);

    // S0 stage 6: K6a
    z_mma<<<dim3(Cc, NB), blk, ZM_SMEM>>>(
        pG2, patt, pg, on_b, on_g, on_bb, on_m, on_v, ph, 0);
    cudaEventRecord(e6, 0);

    // S0 stage 7: K7a
    conv_mma<MODE_BN_RES_LEAKY, 0><<<dim3(Pp / 256, 1, NB), blk, CV_SMEM>>>(
        ph, pwt + WT_FF, ff_b, nullptr, pg, ff_g, ff_bb, ff_m, ff_v,
        out, Cc, Cc, 0);

    // ---- Stream s2: segment B (n 16..31), one stage behind ----
    cudaStreamWaitEvent(s2, e1, 0);   // prep + K1a done -> start K1b beside K2a
    conv_mma<MODE_BIAS, 1><<<dim3(Pp / 256, 1, NB), blk, CV_SMEM, s2>>>(
        x, pwt + WT_GCN, gcn_b, nullptr, nullptr, nullptr, nullptr, nullptr, nullptr,
        ph, Cc, Cc, NB);

    cudaStreamWaitEvent(s2, e2, 0);
    adj_mma<<<dim3((NB * Cc * Tt) / 64, 1, 1), blk, AD_SMEM, s2>>>(
        ph, pA2, x, gcn_g, gcn_bb, gcn_m, gcn_v, pg, NB * Cc * Tt);

    cudaStreamWaitEvent(s2, e3, 0);   // K3a (after wpe on S0) done
    conv_mma<MODE_ADD2D, 1><<<dim3(Pp / 256, 2, NB), blk, CV_SMEM, s2>>>(
        pg, pwt + WT_QKV, nullptr, pwpe, nullptr, nullptr, nullptr, nullptr, nullptr,
        pqk, Cc, OQKV, NB);

    cudaStreamWaitEvent(s2, e4, 0);
    attn_mma<<<dim3(Hh, NB, 4), blk, AT_SMEM, s2>>>(pqk, pattp, NB);
    attn_combine_kernel<<<(NB * Hh * Tt * Tt + 255) / 256, blk, 0, s2>>>(
        pattp, alphas, att1s, patt, NB);

    cudaStreamWaitEvent(s2, e5, 0);
    conv_mma<MODE_NONE, 1><<<dim3(Pp / 256, 3, NB), blk, CV_SMEM, s2>>>(
        pg, pwt + WT_W2, nullptr, nullptr, nullptr, nullptr, nullptr, nullptr, nullptr,
        pG2, Cc, HC, NB);

    cudaStreamWaitEvent(s2, e6, 0);
    z_mma<<<dim3(Cc, NB), blk, ZM_SMEM, s2>>>(
        pG2, patt, pg, on_b, on_g, on_bb, on_m, on_v, ph, NB);

    conv_mma<MODE_BN_RES_LEAKY, 0><<<dim3(Pp / 256, 1, NB), blk, CV_SMEM, s2>>>(
        ph, pwt + WT_FF, ff_b, nullptr, pg, ff_g, ff_bb, ff_m, ff_v,
        out, Cc, Cc, NB);
    cudaEventRecord(evS, s2);

    // join
    cudaStreamWaitEvent(0, evS, 0);
}

// round 13
// speedup vs baseline: 1.1373x; 1.0188x over previous
#include <cuda_runtime.h>
#include <math.h>
#include <stdint.h>

#define Nn   32
#define Cc   64
#define Tt   64
#define Vv   204
#define Hh   3
#define QKd  16
#define Pp   13056
#define OQKV 96
#define HC   192
#define NB   16

__device__ float d_h   [(size_t)Nn * Cc * Pp + 64];
__device__ float d_g   [(size_t)Nn * Cc * Pp + 64];
__device__ float d_qk  [(size_t)Nn * OQKV * Pp + 64];
__device__ float d_wpe [(size_t)OQKV * Pp];
__device__ float d_att [(size_t)Nn * Hh * Tt * Tt];
__device__ float d_attp[(size_t)4 * Nn * Hh * Tt * Tt];
__device__ float d_G2  [(size_t)Nn * HC * Pp + 64];
__device__ float d_wt  [4096 + 6144 + 4096 + 12288];
__device__ float d_A2  [208 * 208];

#define WT_GCN 0
#define WT_QKV 4096
#define WT_FF  10240
#define WT_W2  14336

enum { MODE_BIAS = 0, MODE_ADD2D = 1, MODE_BN_RES_LEAKY = 2, MODE_NONE = 3 };

__device__ __forceinline__ unsigned cvt_tf32(float f) {
    unsigned u; asm("cvt.rna.tf32.f32 %0, %1;" : "=r"(u) : "f"(f)); return u;
}
__device__ __forceinline__ float rna_f(float f) { return __uint_as_float(cvt_tf32(f)); }

__device__ __forceinline__ void mma8(float* d, const unsigned* a, const unsigned* b) {
    asm volatile(
        "mma.sync.aligned.m16n8k8.row.col.f32.tf32.tf32.f32 "
        "{%0,%1,%2,%3},{%4,%5,%6,%7},{%8,%9},{%0,%1,%2,%3};"
        : "+f"(d[0]), "+f"(d[1]), "+f"(d[2]), "+f"(d[3])
        : "r"(a[0]), "r"(a[1]), "r"(a[2]), "r"(a[3]), "r"(b[0]), "r"(b[1]));
}
__device__ __forceinline__ uint32_t smem_u32(const void* p) {
    return (uint32_t)__cvta_generic_to_shared(p);
}
__device__ __forceinline__ void cpa16(uint32_t dst, const void* src) {
    asm volatile("cp.async.cg.shared.global [%0],[%1],16;" :: "r"(dst), "l"(src));
}
__device__ __forceinline__ void cpa16z(uint32_t dst, const void* src, int sz) {
    asm volatile("cp.async.cg.shared.global [%0],[%1],16,%2;" :: "r"(dst), "l"(src), "r"(sz));
}
#define CP_COMMIT() asm volatile("cp.async.commit_group;")
#define CP_WAIT2()  asm volatile("cp.async.wait_group 2;")

// ============================================================================
__global__ void prep_kernel(const float* __restrict__ gcn_w, const float* __restrict__ qkv_w,
                            const float* __restrict__ ff_w, const float* __restrict__ on_w,
                            const float* __restrict__ A,
                            float* __restrict__ wt, float* __restrict__ A2)
{
    int i = blockIdx.x * 256 + threadIdx.x;
    if (i < 4096) { wt[WT_GCN + i] = rna_f(gcn_w[i]); return; }
    i -= 4096;
    if (i < 6144) { wt[WT_QKV + i] = rna_f(qkv_w[i]); return; }
    i -= 6144;
    if (i < 4096) { wt[WT_FF + i] = rna_f(ff_w[i]); return; }
    i -= 4096;
    if (i < 12288) {
        int o = i >> 6, cc = i & 63;
        int s = o >> 6, c = o & 63;
        wt[WT_W2 + i] = rna_f(on_w[(size_t)c * HC + s * 64 + cc]);
        return;
    }
    i -= 12288;
    if (i < 208 * 208) {
        int u = i / 208, v = i % 208;
        A2[i] = (u < 204 && v < 204) ? rna_f(A[(size_t)u * 204 + v]) : 0.f;
    }
}

// ============================================================================
// conv_mma (R5 + batch offset)
// ============================================================================
#define CV_ASZ (64 * 20)
#define CV_BSZ (16 * 264)
#define CV_SMEM (4 * (CV_ASZ + CV_BSZ) * 4)

template <int MODE, int ROUND>
__global__ __launch_bounds__(256, 2)
void conv_mma(const float* __restrict__ in, const float* __restrict__ Wt,
              const float* __restrict__ bias, const float* __restrict__ add2d,
              const float* __restrict__ res,
              const float* __restrict__ bng, const float* __restrict__ bnb,
              const float* __restrict__ bnm, const float* __restrict__ bnv,
              float* __restrict__ out, int Kc, int Oc, int nbase)
{
    extern __shared__ float sm[];
    float* As = sm;
    float* Bs = sm + 4 * CV_ASZ;

    const int n  = blockIdx.z + nbase;
    const int pt = blockIdx.x * 256;
    const int ot = blockIdx.y * 64;
    const int tid = threadIdx.x, lane = tid & 31, warp = tid >> 5;
    const int wm = warp & 1, wn = warp >> 1;
    const int m0 = wm * 32, n0 = wn * 64;
    const int lr = lane >> 2, kc = lane & 3;

    const float* inN = in + (size_t)n * Kc * Pp + pt;
    const int NCH = Kc >> 4;

    float acc[2][8][4];
    #pragma unroll
    for (int f = 0; f < 2; f++)
        #pragma unroll
        for (int j = 0; j < 8; j++)
            #pragma unroll
            for (int q = 0; q < 4; q++) acc[f][j][q] = 0.f;

    auto prefetch = [&](int c, int stage) {
        float* BsS = Bs + stage * CV_BSZ;
        const float* bsrc = inN + (size_t)(c * 16) * Pp;
        #pragma unroll
        for (int i = 0; i < 4; i++) {
            int e = tid + 256 * i;
            int k = e >> 6, grp = e & 63;
            cpa16(smem_u32(&BsS[k * 264 + grp * 4]), bsrc + (size_t)k * Pp + grp * 4);
        }
        float* AsS = As + stage * CV_ASZ;
        int arow = tid >> 2, agrp = tid & 3;
        int o = ot + arow;
        int ok = (o < Oc);
        cpa16z(smem_u32(&AsS[arow * 20 + agrp * 4]),
               ok ? (Wt + (size_t)o * Kc + c * 16 + agrp * 4) : Wt, ok ? 16 : 0);
    };

    prefetch(0, 0); CP_COMMIT();
    if (NCH > 1) prefetch(1, 1);
    CP_COMMIT();

    for (int c = 0; c < NCH; c++) {
        if (c + 2 < NCH) prefetch(c + 2, (c + 2) & 3);
        CP_COMMIT();
        CP_WAIT2();
        __syncthreads();

        const float* AsS = As + (c & 3) * CV_ASZ;
        const float* BsS = Bs + (c & 3) * CV_BSZ;
        #pragma unroll
        for (int g = 0; g < 2; g++) {
            unsigned a[2][4];
            #pragma unroll
            for (int f = 0; f < 2; f++) {
                a[f][0] = __float_as_uint(AsS[(m0 + f * 16 + lr    ) * 20 + g * 8 + kc    ]);
                a[f][1] = __float_as_uint(AsS[(m0 + f * 16 + lr + 8) * 20 + g * 8 + kc    ]);
                a[f][2] = __float_as_uint(AsS[(m0 + f * 16 + lr    ) * 20 + g * 8 + kc + 4]);
                a[f][3] = __float_as_uint(AsS[(m0 + f * 16 + lr + 8) * 20 + g * 8 + kc + 4]);
            }
            #pragma unroll
            for (int j = 0; j < 8; j++) {
                unsigned b[2];
                b[0] = __float_as_uint(BsS[(g * 8 + kc    ) * 264 + n0 + 8 * j + lr]);
                b[1] = __float_as_uint(BsS[(g * 8 + kc + 4) * 264 + n0 + 8 * j + lr]);
                mma8(acc[0][j], a[0], b);
                mma8(acc[1][j], a[1], b);
            }
        }
    }

    #pragma unroll
    for (int f = 0; f < 2; f++) {
        #pragma unroll
        for (int half = 0; half < 2; half++) {
            int o = ot + m0 + f * 16 + lr + half * 8;
            if (o >= Oc) continue;
            size_t obase = ((size_t)n * Oc + o) * Pp;
            if (MODE == MODE_NONE) {
                #pragma unroll
                for (int j = 0; j < 8; j++) {
                    int p = pt + n0 + 8 * j + 2 * kc;
                    float va = acc[f][j][half * 2], vb = acc[f][j][half * 2 + 1];
                    if (ROUND) { va = rna_f(va); vb = rna_f(vb); }
                    *(float2*)(out + obase + p) = make_float2(va, vb);
                }
            } else if (MODE == MODE_BIAS) {
                float b = bias[o];
                #pragma unroll
                for (int j = 0; j < 8; j++) {
                    int p = pt + n0 + 8 * j + 2 * kc;
                    float va = acc[f][j][half * 2] + b, vb = acc[f][j][half * 2 + 1] + b;
                    if (ROUND) { va = rna_f(va); vb = rna_f(vb); }
                    *(float2*)(out + obase + p) = make_float2(va, vb);
                }
            } else if (MODE == MODE_ADD2D) {
                size_t abase = (size_t)o * Pp;
                #pragma unroll
                for (int j = 0; j < 8; j++) {
                    int p = pt + n0 + 8 * j + 2 * kc;
                    float2 av = *(const float2*)(add2d + abase + p);
                    float va = acc[f][j][half * 2] + av.x, vb = acc[f][j][half * 2 + 1] + av.y;
                    if (ROUND) { va = rna_f(va); vb = rna_f(vb); }
                    *(float2*)(out + obase + p) = make_float2(va, vb);
                }
            } else {
                float s  = bng[o] * rsqrtf(bnv[o] + 1e-5f);
                float sh = bnb[o] - bnm[o] * s + bias[o] * s;
                #pragma unroll
                for (int j = 0; j < 8; j++) {
                    int p = pt + n0 + 8 * j + 2 * kc;
                    float2 rv = *(const float2*)(res + obase + p);
                    float va = acc[f][j][half * 2]     * s + sh + rv.x;
                    float vb = acc[f][j][half * 2 + 1] * s + sh + rv.y;
                    va = (va > 0.f) ? va : 0.1f * va;
                    vb = (vb > 0.f) ? vb : 0.1f * vb;
                    if (ROUND) { va = rna_f(va); vb = rna_f(vb); }
                    *(float2*)(out + obase + p) = make_float2(va, vb);
                }
            }
        }
    }
}

// ============================================================================
// adj_mma: M=128 rows/CTA (halves A2 L2 traffic), 512 thr, 16 warps = 8(M)x2(N),
// warp tile m16 x n104 (identical to R5 per-warp shape). 1 CTA/SM.
// ============================================================================
#define AD_ASZ (128 * 20)
#define AD_BSZ (208 * 20)
#define AD_SMEM (4 * (AD_ASZ + AD_BSZ) * 4)

__global__ __launch_bounds__(512, 1)
void adj_mma(const float* __restrict__ h, const float* __restrict__ A2,
             const float* __restrict__ x,
             const float* __restrict__ bng, const float* __restrict__ bnb,
             const float* __restrict__ bnm, const float* __restrict__ bnv,
             float* __restrict__ out, int rbase)
{
    extern __shared__ float sm[];
    float* As = sm;
    float* Bs = sm + 4 * AD_ASZ;

    const int rt = blockIdx.x * 128 + rbase;
    const int tid = threadIdx.x, lane = tid & 31, warp = tid >> 5;
    const int wm = warp & 7, wn = warp >> 3;
    const int m0 = wm * 16, nb0 = wn * 104;
    const int lr = lane >> 2, kc = lane & 3;

    float acc[13][4];
    #pragma unroll
    for (int j = 0; j < 13; j++)
        #pragma unroll
        for (int q = 0; q < 4; q++) acc[j][q] = 0.f;

    const int arow = tid >> 2, agrp = tid & 3;   // 128 rows x 4 k-groups = 512
    const int NCH = 13;

    auto prefetch = [&](int c, int stage) {
        float* BsS = Bs + stage * AD_BSZ;
        #pragma unroll
        for (int i = 0; i < 2; i++) {
            int e = tid + 512 * i;
            if (e < 832) {
                int u = e >> 2, grp = e & 3;
                cpa16(smem_u32(&BsS[u * 20 + grp * 4]), A2 + (size_t)u * 208 + c * 16 + grp * 4);
            }
        }
        float* AsS = As + stage * AD_ASZ;
        cpa16(smem_u32(&AsS[arow * 20 + agrp * 4]),
              h + (size_t)(rt + arow) * 204 + c * 16 + agrp * 4);
    };

    prefetch(0, 0); CP_COMMIT();
    prefetch(1, 1); CP_COMMIT();

    for (int c = 0; c < NCH; c++) {
        if (c + 2 < NCH) prefetch(c + 2, (c + 2) & 3);
        CP_COMMIT();
        CP_WAIT2();
        __syncthreads();

        const float* AsS = As + (c & 3) * AD_ASZ;
        const float* BsS = Bs + (c & 3) * AD_BSZ;
        #pragma unroll
        for (int g = 0; g < 2; g++) {
            unsigned a[4];
            a[0] = __float_as_uint(AsS[(m0 + lr    ) * 20 + g * 8 + kc    ]);
            a[1] = __float_as_uint(AsS[(m0 + lr + 8) * 20 + g * 8 + kc    ]);
            a[2] = __float_as_uint(AsS[(m0 + lr    ) * 20 + g * 8 + kc + 4]);
            a[3] = __float_as_uint(AsS[(m0 + lr + 8) * 20 + g * 8 + kc + 4]);
            #pragma unroll
            for (int j = 0; j < 13; j++) {
                unsigned b[2];
                b[0] = __float_as_uint(BsS[(nb0 + 8 * j + lr) * 20 + g * 8 + kc    ]);
                b[1] = __float_as_uint(BsS[(nb0 + 8 * j + lr) * 20 + g * 8 + kc + 4]);
                mma8(acc[j], a, b);
            }
        }
    }

    #pragma unroll
    for (int half = 0; half < 2; half++) {
        int r = rt + m0 + lr + half * 8;
        int cch = (r >> 6) & 63;
        float s  = bng[cch] * rsqrtf(bnv[cch] + 1e-5f);
        float sh = bnb[cch] - bnm[cch] * s;
        size_t rb = (size_t)r * 204;
        #pragma unroll
        for (int j = 0; j < 13; j++) {
            int u = nb0 + 8 * j + 2 * kc;
            if (u < 204) {
                float2 xv = *(const float2*)(x + rb + u);
                float va = acc[j][half * 2]     * s + sh + xv.x;
                float vb = acc[j][half * 2 + 1] * s + sh + xv.y;
                *(float2*)(out + rb + u) =
                    make_float2(rna_f(fmaxf(va, 0.f)), rna_f(fmaxf(vb, 0.f)));
            }
        }
    }
}

// ============================================================================
// attn_mma / combine / z_mma (R10 verbatim)
// ============================================================================
#define AT_QSZ (64 * 20)
#define AT_SMEM (4 * 2 * AT_QSZ * 4)

__global__ __launch_bounds__(256, 4)
void attn_mma(const float* __restrict__ qk, float* __restrict__ part, int nbase)
{
    extern __shared__ float sm[];
    float* Qs = sm;
    float* Ks = sm + 4 * AT_QSZ;

    const int hh = blockIdx.x, n = blockIdx.y + nbase, z = blockIdx.z;
    const int cc0 = z * 4;
    const int tid = threadIdx.x, lane = tid & 31, warp = tid >> 5;
    const int wm = warp & 3, wn = warp >> 2;
    const int m0 = wm * 16, nb0 = wn * 32;
    const int lr = lane >> 2, kc = lane & 3;

    const float* qbase = qk + ((size_t)n * OQKV + hh * QKd) * Pp;
    const float* kbase = qk + ((size_t)n * OQKV + Hh * QKd + hh * QKd) * Pp;

    const int arow = tid >> 2, agrp = tid & 3;
    const int NCH = 52;

    float acc[4][4];
    #pragma unroll
    for (int j = 0; j < 4; j++)
        #pragma unroll
        for (int q = 0; q < 4; q++) acc[j][q] = 0.f;

    auto prefetch = [&](int c, int stage) {
        int ci = cc0 + (c / 13);
        int vb = (c % 13) * 16;
        int v = vb + agrp * 4;
        int ok = (v < 204);
        const float* qs = qbase + (size_t)ci * Pp + (size_t)arow * 204 + v;
        const float* ks = kbase + (size_t)ci * Pp + (size_t)arow * 204 + v;
        cpa16z(smem_u32(&Qs[stage * AT_QSZ + arow * 20 + agrp * 4]), ok ? qs : qk, ok ? 16 : 0);
        cpa16z(smem_u32(&Ks[stage * AT_QSZ + arow * 20 + agrp * 4]), ok ? ks : qk, ok ? 16 : 0);
    };

    prefetch(0, 0); CP_COMMIT();
    prefetch(1, 1); CP_COMMIT();

    for (int c = 0; c < NCH; c++) {
        if (c + 2 < NCH) prefetch(c + 2, (c + 2) & 3);
        CP_COMMIT();
        CP_WAIT2();
        __syncthreads();

        const float* QsS = Qs + (c & 3) * AT_QSZ;
        const float* KsS = Ks + (c & 3) * AT_QSZ;
        #pragma unroll
        for (int g = 0; g < 2; g++) {
            unsigned a[4];
            a[0] = __float_as_uint(QsS[(m0 + lr    ) * 20 + g * 8 + kc    ]);
            a[1] = __float_as_uint(QsS[(m0 + lr + 8) * 20 + g * 8 + kc    ]);
            a[2] = __float_as_uint(QsS[(m0 + lr    ) * 20 + g * 8 + kc + 4]);
            a[3] = __float_as_uint(QsS[(m0 + lr + 8) * 20 + g * 8 + kc + 4]);
            #pragma unroll
            for (int j = 0; j < 4; j++) {
                unsigned b[2];
                b[0] = __float_as_uint(KsS[(nb0 + 8 * j + lr) * 20 + g * 8 + kc    ]);
                b[1] = __float_as_uint(KsS[(nb0 + 8 * j + lr) * 20 + g * 8 + kc + 4]);
                mma8(acc[j], a, b);
            }
        }
    }

    float* pb = part + (((size_t)z * Nn + n) * Hh + hh) * 4096;
    #pragma unroll
    for (int half = 0; half < 2; half++) {
        int t = m0 + lr + half * 8;
        #pragma unroll
        for (int j = 0; j < 4; j++) {
            int q = nb0 + 8 * j + 2 * kc;
            *(float2*)(pb + (size_t)t * 64 + q) =
                make_float2(acc[j][half * 2], acc[j][half * 2 + 1]);
        }
    }
}

__global__ void attn_combine_kernel(const float* __restrict__ part,
                                    const float* __restrict__ alphas,
                                    const float* __restrict__ att1s,
                                    float* __restrict__ att, int nbase)
{
    int idx = blockIdx.x * blockDim.x + threadIdx.x;
    const int seg_total = NB * Hh * Tt * Tt;
    if (idx >= seg_total) return;
    int tq = idx & (Tt * Tt - 1);
    int rest = idx >> 12;
    int h = rest % Hh;
    int n = nbase + rest / Hh;
    const int total = Nn * Hh * Tt * Tt;
    size_t gi = (((size_t)n * Hh + h) << 12) + tq;
    float p = part[gi] + part[(size_t)total + gi]
            + part[2 * (size_t)total + gi] + part[3 * (size_t)total + gi];
    const float inv = 1.0f / (float)(QKd * Vv);
    att[gi] = rna_f(tanhf(p * inv) * alphas[h] + att1s[(size_t)h * Tt * Tt + tq]);
}

#define ZM_ASZ (16 * 72)
#define ZM_BSZ (16 * 232)
#define ZM_SMEM (4 * (ZM_ASZ + ZM_BSZ) * 4)

__global__ __launch_bounds__(256, 2)
void z_mma(const float* __restrict__ G2, const float* __restrict__ att,
           const float* __restrict__ g,
           const float* __restrict__ on_b, const float* __restrict__ on_g,
           const float* __restrict__ on_bb, const float* __restrict__ on_m,
           const float* __restrict__ on_v,
           float* __restrict__ out, int nbase)
{
    extern __shared__ float sm[];
    float* As = sm;
    float* Bs = sm + 4 * ZM_ASZ;

    const int cch = blockIdx.x, n = blockIdx.y + nbase;
    const int tid = threadIdx.x, lane = tid & 31, warp = tid >> 5;
    const int wm = warp & 3, wn = warp >> 2;
    const int m0 = wm * 16, nb0 = wn * 104;
    const int lr = lane >> 2, kc = lane & 3;

    float acc[13][4];
    #pragma unroll
    for (int j = 0; j < 13; j++)
        #pragma unroll
        for (int q = 0; q < 4; q++) acc[j][q] = 0.f;

    const int NCH = 12;

    auto prefetch = [&](int c, int stage) {
        int s  = c >> 2;
        int tb = (c & 3) * 16;
        const float* gb = G2 + ((size_t)n * HC + s * 64 + cch) * Pp;
        float* BsS = Bs + stage * ZM_BSZ;
        #pragma unroll
        for (int i = 0; i < 4; i++) {
            int e = tid + 256 * i;
            if (e < 832) {
                int trow = e / 52, grp = e % 52;
                int ok = (grp < 51);
                cpa16z(smem_u32(&BsS[trow * 232 + grp * 4]),
                       ok ? (gb + (size_t)(tb + trow) * 204 + grp * 4) : gb, ok ? 16 : 0);
            }
        }
        float* AsS = As + stage * ZM_ASZ;
        int trow = tid >> 4, grp = tid & 15;
        cpa16(smem_u32(&AsS[trow * 72 + grp * 4]),
              att + ((size_t)(n * Hh + s)) * 4096 + (size_t)(tb + trow) * 64 + grp * 4);
    };

    prefetch(0, 0); CP_COMMIT();
    prefetch(1, 1); CP_COMMIT();

    for (int c = 0; c < NCH; c++) {
        if (c + 2 < NCH) prefetch(c + 2, (c + 2) & 3);
        CP_COMMIT();
        CP_WAIT2();
        __syncthreads();

        const float* AsS = As + (c & 3) * ZM_ASZ;
        const float* BsS = Bs + (c & 3) * ZM_BSZ;
        #pragma unroll
        for (int g8 = 0; g8 < 2; g8++) {
            unsigned a[4];
            a[0] = __float_as_uint(AsS[(g8 * 8 + kc    ) * 72 + m0 + lr    ]);
            a[1] = __float_as_uint(AsS[(g8 * 8 + kc    ) * 72 + m0 + lr + 8]);
            a[2] = __float_as_uint(AsS[(g8 * 8 + kc + 4) * 72 + m0 + lr    ]);
            a[3] = __float_as_uint(AsS[(g8 * 8 + kc + 4) * 72 + m0 + lr + 8]);
            #pragma unroll
            for (int j = 0; j < 13; j++) {
                unsigned b[2];
                b[0] = __float_as_uint(BsS[(g8 * 8 + kc    ) * 232 + nb0 + 8 * j + lr]);
                b[1] = __float_as_uint(BsS[(g8 * 8 + kc + 4) * 232 + nb0 + 8 * j + lr]);
                mma8(acc[j], a, b);
            }
        }
    }

    const float sbn = on_g[cch] * rsqrtf(on_v[cch] + 1e-5f);
    const float sh  = on_bb[cch] - on_m[cch] * sbn + on_b[cch] * sbn;
    const float* gres = g + ((size_t)n * Cc + cch) * Pp;
    float* zb = out + ((size_t)n * Cc + cch) * Pp;

    #pragma unroll
    for (int half = 0; half < 2; half++) {
        int q = m0 + lr + half * 8;
        #pragma unroll
        for (int j = 0; j < 13; j++) {
            int v = nb0 + 8 * j + 2 * kc;
            if (v < 204) {
                float2 rv = *(const float2*)(gres + (size_t)q * 204 + v);
                float va = acc[j][half * 2]     * sbn + sh + rv.x;
                float vb = acc[j][half * 2 + 1] * sbn + sh + rv.y;
                va = (va > 0.f) ? va : 0.1f * va;
                vb = (vb > 0.f) ? vb : 0.1f * vb;
                *(float2*)(zb + (size_t)q * 204 + v) = make_float2(rna_f(va), rna_f(vb));
            }
        }
    }
}

// ---------------- launch: two free-running segment chains ----------------
extern "C" void kernel_launch(void* const* d_in, const int* in_sizes, int n_in,
                              void* d_out, int out_size)
{
    const float* x      = (const float*)d_in[0];
    const float* A      = (const float*)d_in[1];
    const float* gcn_w  = (const float*)d_in[2];
    const float* gcn_b  = (const float*)d_in[3];
    const float* gcn_g  = (const float*)d_in[4];
    const float* gcn_bb = (const float*)d_in[5];
    const float* gcn_m  = (const float*)d_in[6];
    const float* gcn_v  = (const float*)d_in[7];
    const float* pe     = (const float*)d_in[8];
    const float* qkv_w  = (const float*)d_in[9];
    const float* qkv_b  = (const float*)d_in[10];
    const float* alphas = (const float*)d_in[11];
    const float* att1s  = (const float*)d_in[12];
    const float* on_w   = (const float*)d_in[13];
    const float* on_b   = (const float*)d_in[14];
    const float* on_g   = (const float*)d_in[15];
    const float* on_bb  = (const float*)d_in[16];
    const float* on_m   = (const float*)d_in[17];
    const float* on_v   = (const float*)d_in[18];
    const float* ff_w   = (const float*)d_in[19];
    const float* ff_b   = (const float*)d_in[20];
    const float* ff_g   = (const float*)d_in[21];
    const float* ff_bb  = (const float*)d_in[22];
    const float* ff_m   = (const float*)d_in[23];
    const float* ff_v   = (const float*)d_in[24];
    float* out = (float*)d_out;

    float *ph, *pg, *pqk, *pwpe, *patt, *pattp, *pG2, *pwt, *pA2;
    cudaGetSymbolAddress((void**)&ph,    d_h);
    cudaGetSymbolAddress((void**)&pg,    d_g);
    cudaGetSymbolAddress((void**)&pqk,   d_qk);
    cudaGetSymbolAddress((void**)&pwpe,  d_wpe);
    cudaGetSymbolAddress((void**)&patt,  d_att);
    cudaGetSymbolAddress((void**)&pattp, d_attp);
    cudaGetSymbolAddress((void**)&pG2,   d_G2);
    cudaGetSymbolAddress((void**)&pwt,   d_wt);
    cudaGetSymbolAddress((void**)&pA2,   d_A2);

    static int init_done = 0;
    static cudaStream_t s2;
    static cudaEvent_t evP, evW, evS;
    if (!init_done) {
        cudaFuncSetAttribute(conv_mma<MODE_BIAS, 0>, cudaFuncAttributeMaxDynamicSharedMemorySize, CV_SMEM);
        cudaFuncSetAttribute(conv_mma<MODE_BIAS, 1>, cudaFuncAttributeMaxDynamicSharedMemorySize, CV_SMEM);
        cudaFuncSetAttribute(conv_mma<MODE_ADD2D, 1>, cudaFuncAttributeMaxDynamicSharedMemorySize, CV_SMEM);
        cudaFuncSetAttribute(conv_mma<MODE_NONE, 1>, cudaFuncAttributeMaxDynamicSharedMemorySize, CV_SMEM);
        cudaFuncSetAttribute(conv_mma<MODE_BN_RES_LEAKY, 0>, cudaFuncAttributeMaxDynamicSharedMemorySize, CV_SMEM);
        cudaFuncSetAttribute(adj_mma, cudaFuncAttributeMaxDynamicSharedMemorySize, AD_SMEM);
        cudaFuncSetAttribute(attn_mma, cudaFuncAttributeMaxDynamicSharedMemorySize, AT_SMEM);
        cudaFuncSetAttribute(z_mma, cudaFuncAttributeMaxDynamicSharedMemorySize, ZM_SMEM);
        cudaStreamCreateWithFlags(&s2, cudaStreamNonBlocking);
        cudaEventCreateWithFlags(&evP, cudaEventDisableTiming);
        cudaEventCreateWithFlags(&evW, cudaEventDisableTiming);
        cudaEventCreateWithFlags(&evS, cudaEventDisableTiming);
        init_done = 1;
    }

    dim3 blk(256), blk5(512);

    // Stream 0: prep + wpe + full chain for segment A (n 0..15)
    prep_kernel<<<(4096 + 6144 + 4096 + 12288 + 208 * 208 + 255) / 256, blk>>>(
        gcn_w, qkv_w, ff_w, on_w, A, pwt, pA2);
    cudaEventRecord(evP, 0);

    conv_mma<MODE_BIAS, 0><<<dim3(Pp / 256, 2, 1), blk, CV_SMEM>>>(
        pe, pwt + WT_QKV, qkv_b, nullptr, nullptr, nullptr, nullptr, nullptr, nullptr,
        pwpe, Cc, OQKV, 0);
    cudaEventRecord(evW, 0);

    conv_mma<MODE_BIAS, 1><<<dim3(Pp / 256, 1, NB), blk, CV_SMEM>>>(
        x, pwt + WT_GCN, gcn_b, nullptr, nullptr, nullptr, nullptr, nullptr, nullptr,
        ph, Cc, Cc, 0);

    adj_mma<<<dim3((NB * Cc * Tt) / 128, 1, 1), blk5, AD_SMEM>>>(
        ph, pA2, x, gcn_g, gcn_bb, gcn_m, gcn_v, pg, 0);

    conv_mma<MODE_ADD2D, 1><<<dim3(Pp / 256, 2, NB), blk, CV_SMEM>>>(
        pg, pwt + WT_QKV, nullptr, pwpe, nullptr, nullptr, nullptr, nullptr, nullptr,
        pqk, Cc, OQKV, 0);

    attn_mma<<<dim3(Hh, NB, 4), blk, AT_SMEM>>>(pqk, pattp, 0);
    attn_combine_kernel<<<(NB * Hh * Tt * Tt + 255) / 256, blk>>>(pattp, alphas, att1s, patt, 0);

    conv_mma<MODE_NONE, 1><<<dim3(Pp / 256, 3, NB), blk, CV_SMEM>>>(
        pg, pwt + WT_W2, nullptr, nullptr, nullptr, nullptr, nullptr, nullptr, nullptr,
        pG2, Cc, HC, 0);

    z_mma<<<dim3(Cc, NB), blk, ZM_SMEM>>>(
        pG2, patt, pg, on_b, on_g, on_bb, on_m, on_v, ph, 0);

    conv_mma<MODE_BN_RES_LEAKY, 0><<<dim3(Pp / 256, 1, NB), blk, CV_SMEM>>>(
        ph, pwt + WT_FF, ff_b, nullptr, pg, ff_g, ff_bb, ff_m, ff_v,
        out, Cc, Cc, 0);

    // Stream s2: full chain for segment B (n 16..31), data-independent
    cudaStreamWaitEvent(s2, evP, 0);
    conv_mma<MODE_BIAS, 1><<<dim3(Pp / 256, 1, NB), blk, CV_SMEM, s2>>>(
        x, pwt + WT_GCN, gcn_b, nullptr, nullptr, nullptr, nullptr, nullptr, nullptr,
        ph, Cc, Cc, NB);

    adj_mma<<<dim3((NB * Cc * Tt) / 128, 1, 1), blk5, AD_SMEM, s2>>>(
        ph, pA2, x, gcn_g, gcn_bb, gcn_m, gcn_v, pg, NB * Cc * Tt);

    cudaStreamWaitEvent(s2, evW, 0);
    conv_mma<MODE_ADD2D, 1><<<dim3(Pp / 256, 2, NB), blk, CV_SMEM, s2>>>(
        pg, pwt + WT_QKV, nullptr, pwpe, nullptr, nullptr, nullptr, nullptr, nullptr,
        pqk, Cc, OQKV, NB);

    attn_mma<<<dim3(Hh, NB, 4), blk, AT_SMEM, s2>>>(pqk, pattp, NB);
    attn_combine_kernel<<<(NB * Hh * Tt * Tt + 255) / 256, blk, 0, s2>>>(
        pattp, alphas, att1s, patt, NB);

    conv_mma<MODE_NONE, 1><<<dim3(Pp / 256, 3, NB), blk, CV_SMEM, s2>>>(
        pg, pwt + WT_W2, nullptr, nullptr, nullptr, nullptr, nullptr, nullptr, nullptr,
        pG2, Cc, HC, NB);

    z_mma<<<dim3(Cc, NB), blk, ZM_SMEM, s2>>>(
        pG2, patt, pg, on_b, on_g, on_bb, on_m, on_v, ph, NB);

    conv_mma<MODE_BN_RES_LEAKY, 0><<<dim3(Pp / 256, 1, NB), blk, CV_SMEM, s2>>>(
        ph, pwt + WT_FF, ff_b, nullptr, pg, ff_g, ff_bb, ff_m, ff_v,
        out, Cc, Cc, NB);
    cudaEventRecord(evS, s2);

    cudaStreamWaitEvent(0, evS, 0);
}